// round 13
// baseline (speedup 1.0000x reference)
#include <cuda_runtime.h>
#include <cuda_fp16.h>
#include <math.h>
#include <stdint.h>

#define B_  32
#define NTOK 197
#define NPATCH 196
#define D_  768
#define H_  12
#define DH  64
#define F_  3072
#define L_  12
#define ROWS  (B_*NTOK)    /* 6304 */
#define PROWS (B_*NPATCH)  /* 6272 */

typedef __half h16;

// single dynamic-shared symbol for the whole TU
extern __shared__ char dynsmem[];

// ---------------- scratch (device globals; no allocation) ----------------
__device__ float g_h[ROWS * D_];

__device__ h16 g_qhi[ROWS * 3 * D_];   // QKV output, hi fp16 plane
__device__ h16 g_qlo[ROWS * 3 * D_];   // QKV output, lo fp16 plane

__device__ h16 g_p16[PROWS * D_];
__device__ h16 g_cw16[D_ * D_];

__device__ h16 g_y16[ROWS * D_];
__device__ h16 g_o16[ROWS * D_];
__device__ h16 g_mid16[ROWS * F_];

__device__ h16 g_oc[B_ * D_];   // compacted cls rows of o16 (last layer)
__device__ h16 g_yc[B_ * D_];   // compacted ln2 output (last layer)

// transposed weights: stored [N][K] per layer
__device__ h16 g_wqkv[L_ * 3 * D_ * D_];
__device__ h16 g_wproj[L_ * D_ * D_];
__device__ h16 g_wfc1[L_ * F_ * D_];
__device__ h16 g_wfc2[L_ * D_ * F_];

// ---------------- helpers ----------------
__device__ __forceinline__ uint32_t smem_u32(const void* p) {
    uint32_t a;
    asm("{ .reg .u64 t; cvta.to.shared.u64 t, %1; cvt.u32.u64 %0, t; }" : "=r"(a) : "l"(p));
    return a;
}
#define SW128(off) ((off) ^ (((off) >> 3) & 0x70))

#define LDSM_X4(r0, r1, r2, r3, addr) \
    asm volatile("ldmatrix.sync.aligned.m8n8.x4.shared.b16 {%0,%1,%2,%3}, [%4];" \
        : "=r"(r0), "=r"(r1), "=r"(r2), "=r"(r3) : "r"(addr))

#define LDSM_X4_T(r0, r1, r2, r3, addr) \
    asm volatile("ldmatrix.sync.aligned.m8n8.x4.trans.shared.b16 {%0,%1,%2,%3}, [%4];" \
        : "=r"(r0), "=r"(r1), "=r"(r2), "=r"(r3) : "r"(addr))

#define MMA16816(d, a, b0, b1) \
    asm volatile("mma.sync.aligned.m16n8k16.row.col.f32.f16.f16.f32 " \
        "{%0,%1,%2,%3}, {%4,%5,%6,%7}, {%8,%9}, {%0,%1,%2,%3};" \
        : "+f"((d)[0]), "+f"((d)[1]), "+f"((d)[2]), "+f"((d)[3]) \
        : "r"((a)[0]), "r"((a)[1]), "r"((a)[2]), "r"((a)[3]), "r"(b0), "r"(b1))

#define CP_ASYNC16(dst, src, sz) \
    asm volatile("cp.async.cg.shared.global [%0], [%1], 16, %2;" \
        :: "r"(dst), "l"(src), "r"(sz) : "memory")

__device__ __forceinline__ uint32_t pack_h2(h16 a, h16 b) {
    __half2 t = __halves2half2(a, b);
    return *(uint32_t*)&t;
}

// ---------------- tensor-core GEMM via mma.sync (fp16 in, fp32 accum) ----------------
// 3-stage cp.async pipeline, 128x128 tile, 256 threads, 2 CTA/SM.
// modes: 0 = outf = v ; 1 = hres += v ; 2 = gelu(v)->o16 ;
//        3 = patch-embed fused assemble: hres[b*197+t+1] = v + pos
//        5 = cls-row residual: hres[(row*197)*768 + col] += v   (M = 32, N = 768)
//        6 = hi/lo fp16 split: o16 = hi(v), olo16 = lo(v)
#define GSTAGE 32768
#define GSMEM_SZ (3 * GSTAGE)

__global__ void __launch_bounds__(256, 2) gemm_mma_kernel(
    const h16* __restrict__ A, const h16* __restrict__ Bw,
    const float* __restrict__ bias,
    float* __restrict__ outf, float* __restrict__ hres,
    h16* __restrict__ o16, h16* __restrict__ olo16,
    const float* __restrict__ posp,
    int M, int N, int K, int mode)
{
    const uint32_t sbase = smem_u32(dynsmem);
    const int tid = threadIdx.x;
    const int bm = blockIdx.y * 128;
    const int bn = blockIdx.x * 128;
    const int NC = K >> 6;
    const int w = tid >> 5, lane = tid & 31;
    const int wm = w & 3, wn = w >> 2;

    float acc[2][8][4];
#pragma unroll
    for (int mt = 0; mt < 2; mt++)
#pragma unroll
        for (int nt = 0; nt < 8; nt++)
#pragma unroll
            for (int r = 0; r < 4; r++) acc[mt][nt][r] = 0.f;

    auto load_stage = [&](int c, int slot) {
        const uint32_t sb = sbase + (uint32_t)slot * GSTAGE;
        const int k0 = c * 64;
#pragma unroll
        for (int t = 0; t < 2; t++) {
#pragma unroll
            for (int i = 0; i < 4; i++) {
                int s = tid + i * 256;
                int r = s >> 3, seg = s & 7;
                int grow = (t == 0) ? (bm + r) : (bn + r);
                int sz = 16;
                if (t == 0 && grow >= M) { grow = 0; sz = 0; }
                const h16* src = (t == 0 ? A : Bw) + (size_t)grow * K + k0 + seg * 8;
                uint32_t dst = sb + t * 16384 + SW128((uint32_t)(r * 128 + seg * 16));
                CP_ASYNC16(dst, src, sz);
            }
        }
        asm volatile("cp.async.commit_group;" ::: "memory");
    };

    load_stage(0, 0);
    if (NC > 1) load_stage(1, 1);

    int slot = 0;
    for (int c = 0; c < NC; c++) {
        if (c + 1 < NC) {
            asm volatile("cp.async.wait_group 1;" ::: "memory");
        } else {
            asm volatile("cp.async.wait_group 0;" ::: "memory");
        }
        __syncthreads();

        if (c + 2 < NC) {
            int ns = slot + 2;
            if (ns >= 3) ns -= 3;
            load_stage(c + 2, ns);
        }

        const uint32_t sb = sbase + (uint32_t)slot * GSTAGE;
        const uint32_t sa = sb, sbw = sb + 16384;

#pragma unroll
        for (int k16 = 0; k16 < 4; k16++) {
            const int kc = k16 * 16;
            uint32_t Af[2][4];
#pragma unroll
            for (int mt = 0; mt < 2; mt++) {
                uint32_t aoff = SW128((uint32_t)((wm * 32 + mt * 16 + (lane & 15)) * 128
                                                 + (kc + (lane >> 4) * 8) * 2));
                LDSM_X4(Af[mt][0], Af[mt][1], Af[mt][2], Af[mt][3], sa + aoff);
            }
            const int sub = lane >> 3, r8 = lane & 7;
            const int nloc = ((sub & 2) ? 8 : 0) + r8;
            const int kloc = kc + (sub & 1) * 8;
#pragma unroll
            for (int ng = 0; ng < 4; ng++) {
                uint32_t boff = SW128((uint32_t)((wn * 64 + ng * 16 + nloc) * 128 + kloc * 2));
                uint32_t Bf[4];
                LDSM_X4(Bf[0], Bf[1], Bf[2], Bf[3], sbw + boff);
#pragma unroll
                for (int mt = 0; mt < 2; mt++) {
#pragma unroll
                    for (int half = 0; half < 2; half++) {
                        const int nt = ng * 2 + half;
                        MMA16816(acc[mt][nt], Af[mt], Bf[half * 2], Bf[half * 2 + 1]);
                    }
                }
            }
        }

        slot++;
        if (slot >= 3) slot = 0;
    }

    // ---- epilogue ----
#pragma unroll
    for (int mt = 0; mt < 2; mt++) {
        const int r0 = bm + wm * 32 + mt * 16 + (lane >> 2);
#pragma unroll
        for (int nt = 0; nt < 8; nt++) {
            const int col = bn + wn * 64 + nt * 8 + (lane & 3) * 2;
            const float b0 = bias[col], b1 = bias[col + 1];
#pragma unroll
            for (int rr = 0; rr < 2; rr++) {
                const int row = r0 + rr * 8;
                if (row >= M) continue;
                float v0 = acc[mt][nt][rr * 2 + 0] + b0;
                float v1 = acc[mt][nt][rr * 2 + 1] + b1;
                size_t oi = (size_t)row * N + col;
                if (mode == 0) {
                    *(float2*)(outf + oi) = make_float2(v0, v1);
                } else if (mode == 1) {
                    float2* hp = (float2*)(hres + oi);
                    float2 t = *hp;
                    t.x += v0; t.y += v1;
                    *hp = t;
                } else if (mode == 2) {
                    float g0 = 0.5f * v0 * (1.0f + erff(v0 * 0.70710678118654752f));
                    float g1 = 0.5f * v1 * (1.0f + erff(v1 * 0.70710678118654752f));
                    __half2 hv = __floats2half2_rn(g0, g1);
                    *(uint32_t*)(o16 + oi) = *(uint32_t*)&hv;
                } else if (mode == 3) {
                    int bb = row / NPATCH;
                    int tt = row - bb * NPATCH;
                    size_t hrow = (size_t)(bb * NTOK + tt + 1);
                    const float* pp = posp + (size_t)(tt + 1) * D_ + col;
                    float2 o = make_float2(v0 + pp[0], v1 + pp[1]);
                    *(float2*)(hres + hrow * D_ + col) = o;
                } else if (mode == 5) {
                    size_t hrow = (size_t)row * NTOK;
                    float2* hp = (float2*)(hres + hrow * D_ + col);
                    float2 t = *hp;
                    t.x += v0; t.y += v1;
                    *hp = t;
                } else {
                    // mode 6: hi/lo fp16 split (QKV for attention)
                    h16 h0 = __float2half_rn(v0), h1 = __float2half_rn(v1);
                    *(uint32_t*)(o16 + oi) = pack_h2(h0, h1);
                    *(uint32_t*)(olo16 + oi) =
                        pack_h2(__float2half_rn(v0 - __half2float(h0)),
                                __float2half_rn(v1 - __half2float(h1)));
                }
            }
        }
    }
}

// ---------------- cls row init: h[b*197] = cls + pos[0] ----------------
__global__ void cls_init_kernel(const float* __restrict__ cls, const float* __restrict__ pos,
                                float* __restrict__ h) {
    int i = blockIdx.x * blockDim.x + threadIdx.x;
    if (i < B_ * D_) {
        int b = i / D_, d = i - b * D_;
        h[(size_t)(b * NTOK) * D_ + d] = cls[d] + pos[d];
    }
}

// ---------------- gather cls rows of o16 into compact buffer ----------------
__global__ void gather_cls_kernel(const h16* __restrict__ o16, h16* __restrict__ oc) {
    int i = blockIdx.x * blockDim.x + threadIdx.x;
    if (i < B_ * D_) {
        int b = i / D_, d = i - b * D_;
        oc[i] = o16[(size_t)(b * NTOK) * D_ + d];
    }
}

// ---------------- batched weight transpose + fp16 (vectorized 128B stores) ----------------
__global__ void wsplit_all_kernel(const float* __restrict__ W, h16* __restrict__ WT,
                                  int K, int N) {
    __shared__ float t[64][33];
    const size_t off = (size_t)blockIdx.z * K * N;
    const float* Wl = W + off;
    h16* WTl = WT + off;
    const int n0 = blockIdx.x * 32, k0 = blockIdx.y * 64;
    const int tx = threadIdx.x, ty = threadIdx.y;
#pragma unroll
    for (int j = 0; j < 8; j++) {
        int kk = ty + 8 * j;
        t[kk][tx] = Wl[(size_t)(k0 + kk) * N + n0 + tx];
    }
    __syncthreads();
#pragma unroll
    for (int j = 0; j < 4; j++) {
        int nl = ty + 8 * j;
        int kl = tx * 2;
        __half2 hv = __floats2half2_rn(t[kl][nl], t[kl + 1][nl]);
        *(uint32_t*)(WTl + (size_t)(n0 + nl) * K + k0 + kl) = *(uint32_t*)&hv;
    }
}

__global__ void split_kernel(const float* __restrict__ W, h16* __restrict__ o, int total) {
    for (int i = blockIdx.x * blockDim.x + threadIdx.x; i < total; i += gridDim.x * blockDim.x)
        o[i] = __float2half(W[i]);
}

// ---------------- patch extraction (fp16, float4 vectorized) ----------------
__global__ void extract_patches_kernel(const float* __restrict__ x, h16* __restrict__ p16) {
    const int total = PROWS * D_ / 4;
    for (int i = blockIdx.x * blockDim.x + threadIdx.x; i < total; i += gridDim.x * blockDim.x) {
        int idx = i * 4;
        int row = idx / D_;
        int k   = idx % D_;
        int b   = row / NPATCH;
        int t   = row % NPATCH;
        int ph  = t / 14, pw = t % 14;
        int cin = k >> 8;
        int rem = k & 255;
        int py  = rem >> 4, px = rem & 15;
        size_t src = (((size_t)b * 3 + cin) * 224 + (ph * 16 + py)) * 224 + (pw * 16 + px);
        float4 v = *(const float4*)(x + src);
        __half2 h0 = __floats2half2_rn(v.x, v.y);
        __half2 h1 = __floats2half2_rn(v.z, v.w);
        uint2 u;
        u.x = *(uint32_t*)&h0;
        u.y = *(uint32_t*)&h1;
        *(uint2*)(p16 + idx) = u;
    }
}

// ---------------- LayerNorm (fp32 out, final rows) ----------------
__global__ void ln_kernel(const float* __restrict__ x, const float* __restrict__ w,
                          const float* __restrict__ b, float* __restrict__ y,
                          int D, int inStride, int outStride) {
    const int row = blockIdx.x;
    const float* xr = x + (size_t)row * inStride;
    float* yr = y + (size_t)row * outStride;
    const int tid = threadIdx.x;
    float s = 0.f, q = 0.f;
    for (int i = tid; i < D; i += blockDim.x) { float v = xr[i]; s += v; q += v * v; }
    for (int o = 16; o; o >>= 1) { s += __shfl_xor_sync(~0u, s, o); q += __shfl_xor_sync(~0u, q, o); }
    __shared__ float ss[8], sq[8], mean_s, rstd_s;
    int wid = tid >> 5, lane = tid & 31;
    if (lane == 0) { ss[wid] = s; sq[wid] = q; }
    __syncthreads();
    if (tid == 0) {
        float ts = 0.f, tq = 0.f;
        for (int i = 0; i < (int)(blockDim.x >> 5); i++) { ts += ss[i]; tq += sq[i]; }
        float m = ts / D;
        mean_s = m;
        rstd_s = rsqrtf(tq / D - m * m + 1e-6f);
    }
    __syncthreads();
    float m = mean_s, rs = rstd_s;
    for (int i = tid; i < D; i += blockDim.x)
        yr[i] = (xr[i] - m) * rs * w[i] + b[i];
}

// ---------------- warp-per-row LayerNorm -> fp16 (D=768), strided ----------------
__global__ void __launch_bounds__(256) ln_h_warp_kernel(
    const float* __restrict__ x, const float* __restrict__ wv,
    const float* __restrict__ bv, h16* __restrict__ y16, int rows,
    size_t inStride, size_t outStride)
{
    const int row = blockIdx.x * 8 + (threadIdx.x >> 5);
    if (row >= rows) return;
    const int lane = threadIdx.x & 31;
    const float4* xr = (const float4*)(x + (size_t)row * inStride);
    float4 vals[6];
    float s = 0.f, q = 0.f;
#pragma unroll
    for (int k = 0; k < 6; k++) {
        float4 v = xr[lane + 32 * k];
        vals[k] = v;
        s += v.x + v.y + v.z + v.w;
        q += v.x * v.x + v.y * v.y + v.z * v.z + v.w * v.w;
    }
#pragma unroll
    for (int o = 16; o; o >>= 1) {
        s += __shfl_xor_sync(~0u, s, o);
        q += __shfl_xor_sync(~0u, q, o);
    }
    const float m = s / D_;
    const float rs = rsqrtf(q / D_ - m * m + 1e-6f);
    uint2* yo = (uint2*)(y16 + (size_t)row * outStride);
    const float4* w4 = (const float4*)wv;
    const float4* b4 = (const float4*)bv;
#pragma unroll
    for (int k = 0; k < 6; k++) {
        float4 v = vals[k];
        float4 ww = w4[lane + 32 * k];
        float4 bb = b4[lane + 32 * k];
        __half2 lo = __floats2half2_rn((v.x - m) * rs * ww.x + bb.x,
                                       (v.y - m) * rs * ww.y + bb.y);
        __half2 hi = __floats2half2_rn((v.z - m) * rs * ww.z + bb.z,
                                       (v.w - m) * rs * ww.w + bb.w);
        uint2 u;
        u.x = *(uint32_t*)&lo;
        u.y = *(uint32_t*)&hi;
        yo[lane + 32 * k] = u;
    }
}

// ---------------- attention: HMMA with 3-product hi/lo splits ----------------
// QKV arrives pre-split (qhi/qlo fp16 planes) -> staging is pure cp.async.
#define ASLAB 26624
#define AMMA_SMEM (6 * ASLAB)
__global__ void __launch_bounds__(256) attn_kernel(const h16* __restrict__ qhi,
                                                   const h16* __restrict__ qlo,
                                                   h16* __restrict__ o16, int ngroups) {
    char* sm = dynsmem;
    const uint32_t sbase = smem_u32(sm);
    // slabs: 0 Qh, 1 Ql, 2 Kh, 3 Kl, 4 Vh, 5 Vl
    const uint32_t Qh = sbase,      Ql = Qh + ASLAB;
    const uint32_t Kh = Ql + ASLAB, Kl = Kh + ASLAB;
    const uint32_t Vh = Kl + ASLAB, Vl = Vh + ASLAB;

    const int bh = blockIdx.x;
    const int b = bh / H_;
    const int h = bh % H_;
    const int tid = threadIdx.x;
    const int lane = tid & 31;
    const int w = tid >> 5;

    // ---- stage all 6 slabs via cp.async (zero-fill rows >= NTOK) ----
    {
        const size_t rowbase = (size_t)b * NTOK * (3 * D_) + h * DH;
        for (int idx = tid; idx < 6 * 208 * 8; idx += 256) {
            int slab = idx / (208 * 8);
            int rem = idx - slab * (208 * 8);
            int m = rem >> 3, seg = rem & 7;
            const h16* srcb = (slab & 1) ? qlo : qhi;
            const h16* src = srcb + rowbase + (size_t)m * (3 * D_) + (slab >> 1) * D_ + seg * 8;
            uint32_t dst = sbase + slab * ASLAB + SW128((uint32_t)(m * 128 + seg * 16));
            int sz = (m < NTOK) ? 16 : 0;
            CP_ASYNC16(dst, src, sz);
        }
        asm volatile("cp.async.commit_group;" ::: "memory");
        asm volatile("cp.async.wait_group 0;" ::: "memory");
    }
    __syncthreads();

    const int c0 = (lane & 3) * 2;

    for (int mt = w; mt < ngroups; mt += 8) {
        float accS[26][4];
#pragma unroll
        for (int t = 0; t < 26; t++)
#pragma unroll
            for (int i = 0; i < 4; i++) accS[t][i] = 0.f;

#pragma unroll
        for (int kc = 0; kc < 4; kc++) {
            uint32_t Ah4[4], Al4[4];
            {
                uint32_t aoff = SW128((uint32_t)((mt * 16 + (lane & 15)) * 128
                                                 + (kc * 16 + (lane >> 4) * 8) * 2));
                LDSM_X4(Ah4[0], Ah4[1], Ah4[2], Ah4[3], Qh + aoff);
                LDSM_X4(Al4[0], Al4[1], Al4[2], Al4[3], Ql + aoff);
            }
            const int sub = lane >> 3, r8 = lane & 7;
            const int nloc = ((sub & 2) ? 8 : 0) + r8;
            const int kloc = kc * 16 + (sub & 1) * 8;
#pragma unroll
            for (int np = 0; np < 13; np++) {
                uint32_t boff = SW128((uint32_t)((np * 16 + nloc) * 128 + kloc * 2));
                uint32_t BH[4], BL[4];
                LDSM_X4(BH[0], BH[1], BH[2], BH[3], Kh + boff);
                LDSM_X4(BL[0], BL[1], BL[2], BL[3], Kl + boff);
                MMA16816(accS[2 * np], Ah4, BH[0], BH[1]);
                MMA16816(accS[2 * np], Ah4, BL[0], BL[1]);
                MMA16816(accS[2 * np], Al4, BH[0], BH[1]);
                MMA16816(accS[2 * np + 1], Ah4, BH[2], BH[3]);
                MMA16816(accS[2 * np + 1], Ah4, BL[2], BL[3]);
                MMA16816(accS[2 * np + 1], Al4, BH[2], BH[3]);
            }
        }

        float mx0 = -1e30f, mx1 = -1e30f;
#pragma unroll
        for (int t = 0; t < 26; t++) {
#pragma unroll
            for (int i = 0; i < 4; i++) {
                int col = t * 8 + c0 + (i & 1);
                float s = (col < NTOK) ? (accS[t][i] * 0.125f) : -1e30f;
                accS[t][i] = s;
                if (i < 2) mx0 = fmaxf(mx0, s);
                else       mx1 = fmaxf(mx1, s);
            }
        }
        mx0 = fmaxf(mx0, __shfl_xor_sync(~0u, mx0, 1));
        mx0 = fmaxf(mx0, __shfl_xor_sync(~0u, mx0, 2));
        mx1 = fmaxf(mx1, __shfl_xor_sync(~0u, mx1, 1));
        mx1 = fmaxf(mx1, __shfl_xor_sync(~0u, mx1, 2));
        float sum0 = 0.f, sum1 = 0.f;
#pragma unroll
        for (int t = 0; t < 26; t++) {
#pragma unroll
            for (int i = 0; i < 4; i++) {
                float e = expf(accS[t][i] - ((i < 2) ? mx0 : mx1));
                accS[t][i] = e;
                if (i < 2) sum0 += e;
                else       sum1 += e;
            }
        }
        sum0 += __shfl_xor_sync(~0u, sum0, 1);
        sum0 += __shfl_xor_sync(~0u, sum0, 2);
        sum1 += __shfl_xor_sync(~0u, sum1, 1);
        sum1 += __shfl_xor_sync(~0u, sum1, 2);
        const float inv0 = 1.f / sum0, inv1 = 1.f / sum1;

        float accO[8][4];
#pragma unroll
        for (int nt = 0; nt < 8; nt++)
#pragma unroll
            for (int i = 0; i < 4; i++) accO[nt][i] = 0.f;

        const int g = lane >> 3;
        const int vrow_loc = (g & 1) * 8 + (lane & 7);
        const int vcol_b = (g >> 1) * 16;

#pragma unroll
        for (int kk = 0; kk < 13; kk++) {
            float e0 = accS[2 * kk][0] * inv0, e1 = accS[2 * kk][1] * inv0;
            float e2 = accS[2 * kk][2] * inv1, e3 = accS[2 * kk][3] * inv1;
            float f0 = accS[2 * kk + 1][0] * inv0, f1 = accS[2 * kk + 1][1] * inv0;
            float f2 = accS[2 * kk + 1][2] * inv1, f3 = accS[2 * kk + 1][3] * inv1;
            h16 he0 = __float2half_rn(e0), he1 = __float2half_rn(e1);
            h16 he2 = __float2half_rn(e2), he3 = __float2half_rn(e3);
            h16 hf0 = __float2half_rn(f0), hf1 = __float2half_rn(f1);
            h16 hf2 = __float2half_rn(f2), hf3 = __float2half_rn(f3);
            uint32_t aH[4] = { pack_h2(he0, he1), pack_h2(he2, he3),
                               pack_h2(hf0, hf1), pack_h2(hf2, hf3) };
            uint32_t aL[4] = {
                pack_h2(__float2half_rn(e0 - __half2float(he0)), __float2half_rn(e1 - __half2float(he1))),
                pack_h2(__float2half_rn(e2 - __half2float(he2)), __float2half_rn(e3 - __half2float(he3))),
                pack_h2(__float2half_rn(f0 - __half2float(hf0)), __float2half_rn(f1 - __half2float(hf1))),
                pack_h2(__float2half_rn(f2 - __half2float(hf2)), __float2half_rn(f3 - __half2float(hf3))) };

            const int vrow = kk * 16 + vrow_loc;
#pragma unroll
            for (int vg = 0; vg < 4; vg++) {
                uint32_t voff = SW128((uint32_t)(vrow * 128 + vg * 32 + vcol_b));
                uint32_t VH[4], VL[4];
                LDSM_X4_T(VH[0], VH[1], VH[2], VH[3], Vh + voff);
                LDSM_X4_T(VL[0], VL[1], VL[2], VL[3], Vl + voff);
                MMA16816(accO[vg * 2], aH, VH[0], VH[1]);
                MMA16816(accO[vg * 2], aH, VL[0], VL[1]);
                MMA16816(accO[vg * 2], aL, VH[0], VH[1]);
                MMA16816(accO[vg * 2 + 1], aH, VH[2], VH[3]);
                MMA16816(accO[vg * 2 + 1], aH, VL[2], VL[3]);
                MMA16816(accO[vg * 2 + 1], aL, VH[2], VH[3]);
            }
        }

        const int r1 = mt * 16 + (lane >> 2);
        const int r2 = r1 + 8;
#pragma unroll
        for (int nt = 0; nt < 8; nt++) {
            const int col = h * DH + nt * 8 + c0;
            if (r1 < NTOK) {
                __half2 v = __floats2half2_rn(accO[nt][0], accO[nt][1]);
                *(uint32_t*)(o16 + (size_t)(b * NTOK + r1) * D_ + col) = *(uint32_t*)&v;
            }
            if (r2 < NTOK) {
                __half2 v = __floats2half2_rn(accO[nt][2], accO[nt][3]);
                *(uint32_t*)(o16 + (size_t)(b * NTOK + r2) * D_ + col) = *(uint32_t*)&v;
            }
        }
    }
}

// ---------------- host ----------------
extern "C" void kernel_launch(void* const* d_in, const int* in_sizes, int n_in,
                              void* d_out, int out_size) {
    const float* x       = (const float*)d_in[0];
    const float* conv_w  = (const float*)d_in[1];
    const float* conv_b  = (const float*)d_in[2];
    const float* cls_tok = (const float*)d_in[3];
    const float* pos     = (const float*)d_in[4];
    const float* ln1w    = (const float*)d_in[5];
    const float* ln1b    = (const float*)d_in[6];
    const float* qkvw    = (const float*)d_in[7];
    const float* qkvb    = (const float*)d_in[8];
    const float* projw   = (const float*)d_in[9];
    const float* projb   = (const float*)d_in[10];
    const float* ln2w    = (const float*)d_in[11];
    const float* ln2b    = (const float*)d_in[12];
    const float* fc1w    = (const float*)d_in[13];
    const float* fc1b    = (const float*)d_in[14];
    const float* fc2w    = (const float*)d_in[15];
    const float* fc2b    = (const float*)d_in[16];
    const float* lnfw    = (const float*)d_in[17];
    const float* lnfb    = (const float*)d_in[18];

    float *h;
    h16 *qhi, *qlo, *p16, *cw16, *y16, *o16, *mid16, *oc, *yc;
    h16 *wq, *wp, *w1, *w2;
    cudaGetSymbolAddress((void**)&h,     g_h);
    cudaGetSymbolAddress((void**)&qhi,   g_qhi);
    cudaGetSymbolAddress((void**)&qlo,   g_qlo);
    cudaGetSymbolAddress((void**)&p16,   g_p16);
    cudaGetSymbolAddress((void**)&cw16,  g_cw16);
    cudaGetSymbolAddress((void**)&y16,   g_y16);
    cudaGetSymbolAddress((void**)&o16,   g_o16);
    cudaGetSymbolAddress((void**)&mid16, g_mid16);
    cudaGetSymbolAddress((void**)&oc,    g_oc);
    cudaGetSymbolAddress((void**)&yc,    g_yc);
    cudaGetSymbolAddress((void**)&wq,    g_wqkv);
    cudaGetSymbolAddress((void**)&wp,    g_wproj);
    cudaGetSymbolAddress((void**)&w1,    g_wfc1);
    cudaGetSymbolAddress((void**)&w2,    g_wfc2);

    cudaFuncSetAttribute(attn_kernel, cudaFuncAttributeMaxDynamicSharedMemorySize, AMMA_SMEM);
    cudaFuncSetAttribute(gemm_mma_kernel, cudaFuncAttributeMaxDynamicSharedMemorySize, GSMEM_SZ);

    // ---- weight conversion (transpose + fp16), batched over layers ----
    {
        dim3 blk(32, 8);
        wsplit_all_kernel<<<dim3(3 * D_ / 32, D_ / 64, L_), blk>>>(qkvw, wq, D_, 3 * D_);
        wsplit_all_kernel<<<dim3(D_ / 32, D_ / 64, L_), blk>>>(projw, wp, D_, D_);
        wsplit_all_kernel<<<dim3(F_ / 32, D_ / 64, L_), blk>>>(fc1w, w1, D_, F_);
        wsplit_all_kernel<<<dim3(D_ / 32, F_ / 64, L_), blk>>>(fc2w, w2, F_, D_);
        split_kernel<<<1024, 256>>>(conv_w, cw16, D_ * D_);
    }

    // ---- patch embed: GEMM with fused assemble (mode 3) + cls rows ----
    extract_patches_kernel<<<1024, 256>>>(x, p16);
    cls_init_kernel<<<(B_ * D_ + 255) / 256, 256>>>(cls_tok, pos, h);
    gemm_mma_kernel<<<dim3(D_ / 128, PROWS / 128), 256, GSMEM_SZ>>>(
        p16, cw16, conv_b, nullptr, h, nullptr, nullptr, pos, PROWS, D_, D_, 3);

    const int mb = (ROWS + 127) / 128;   // 50
    const int lnb = (ROWS + 7) / 8;      // 788
    for (int l = 0; l < L_; l++) {
        const bool last = (l == L_ - 1);

        ln_h_warp_kernel<<<lnb, 256>>>(h, ln1w + l * D_, ln1b + l * D_, y16, ROWS,
                                       (size_t)D_, (size_t)D_);
        gemm_mma_kernel<<<dim3(3 * D_ / 128, mb), 256, GSMEM_SZ>>>(
            y16, wq + (size_t)l * 3 * D_ * D_, qkvb + (size_t)l * 3 * D_,
            nullptr, nullptr, qhi, qlo, nullptr, ROWS, 3 * D_, D_, 6);
        attn_kernel<<<B_ * H_, 256, AMMA_SMEM>>>(qhi, qlo, o16, last ? 1 : 13);

        if (!last) {
            gemm_mma_kernel<<<dim3(D_ / 128, mb), 256, GSMEM_SZ>>>(
                o16, wp + (size_t)l * D_ * D_, projb + (size_t)l * D_,
                nullptr, h, nullptr, nullptr, nullptr, ROWS, D_, D_, 1);
            ln_h_warp_kernel<<<lnb, 256>>>(h, ln2w + l * D_, ln2b + l * D_, y16, ROWS,
                                           (size_t)D_, (size_t)D_);
            gemm_mma_kernel<<<dim3(F_ / 128, mb), 256, GSMEM_SZ>>>(
                y16, w1 + (size_t)l * F_ * D_, fc1b + (size_t)l * F_,
                nullptr, nullptr, mid16, nullptr, nullptr, ROWS, F_, D_, 2);
            gemm_mma_kernel<<<dim3(D_ / 128, mb), 256, GSMEM_SZ>>>(
                mid16, w2 + (size_t)l * D_ * F_, fc2b + (size_t)l * D_,
                nullptr, h, nullptr, nullptr, nullptr, ROWS, D_, F_, 1);
        } else {
            gather_cls_kernel<<<(B_ * D_ + 255) / 256, 256>>>(o16, oc);
            gemm_mma_kernel<<<dim3(D_ / 128, 1), 256, GSMEM_SZ>>>(
                oc, wp + (size_t)l * D_ * D_, projb + (size_t)l * D_,
                nullptr, h, nullptr, nullptr, nullptr, B_, D_, D_, 5);
            ln_h_warp_kernel<<<(B_ + 7) / 8, 256>>>(h, ln2w + l * D_, ln2b + l * D_, yc, B_,
                                                    (size_t)NTOK * D_, (size_t)D_);
            gemm_mma_kernel<<<dim3(F_ / 128, 1), 256, GSMEM_SZ>>>(
                yc, w1 + (size_t)l * F_ * D_, fc1b + (size_t)l * F_,
                nullptr, nullptr, mid16, nullptr, nullptr, B_, F_, D_, 2);
            gemm_mma_kernel<<<dim3(D_ / 128, 1), 256, GSMEM_SZ>>>(
                mid16, w2 + (size_t)l * D_ * F_, fc2b + (size_t)l * D_,
                nullptr, h, nullptr, nullptr, nullptr, B_, D_, F_, 5);
        }
    }

    ln_kernel<<<B_, 256>>>(h, lnfw, lnfb, (float*)d_out, D_, NTOK * D_, D_);
}

// round 14
// speedup vs baseline: 1.0156x; 1.0156x over previous
#include <cuda_runtime.h>
#include <cuda_fp16.h>
#include <math.h>
#include <stdint.h>

#define B_  32
#define NTOK 197
#define NPATCH 196
#define D_  768
#define H_  12
#define DH  64
#define F_  3072
#define L_  12
#define ROWS  (B_*NTOK)    /* 6304 */
#define PROWS (B_*NPATCH)  /* 6272 */

typedef __half h16;

// single dynamic-shared symbol for the whole TU
extern __shared__ char dynsmem[];

// ---------------- scratch (device globals; no allocation) ----------------
__device__ float g_h[ROWS * D_];
__device__ float g_qkv[ROWS * 3 * D_];

__device__ h16 g_p16[PROWS * D_];
__device__ h16 g_cw16[D_ * D_];

__device__ h16 g_y16[ROWS * D_];
__device__ h16 g_o16[ROWS * D_];
__device__ h16 g_mid16[ROWS * F_];

__device__ h16 g_oc[B_ * D_];   // compacted cls rows of o16 (last layer)
__device__ h16 g_yc[B_ * D_];   // compacted ln2 output (last layer)

// transposed weights: stored [N][K] per layer
__device__ h16 g_wqkv[L_ * 3 * D_ * D_];
__device__ h16 g_wproj[L_ * D_ * D_];
__device__ h16 g_wfc1[L_ * F_ * D_];
__device__ h16 g_wfc2[L_ * D_ * F_];

// ---------------- helpers ----------------
__device__ __forceinline__ uint32_t smem_u32(const void* p) {
    uint32_t a;
    asm("{ .reg .u64 t; cvta.to.shared.u64 t, %1; cvt.u32.u64 %0, t; }" : "=r"(a) : "l"(p));
    return a;
}
#define SW128(off) ((off) ^ (((off) >> 3) & 0x70))

#define LDSM_X4(r0, r1, r2, r3, addr) \
    asm volatile("ldmatrix.sync.aligned.m8n8.x4.shared.b16 {%0,%1,%2,%3}, [%4];" \
        : "=r"(r0), "=r"(r1), "=r"(r2), "=r"(r3) : "r"(addr))

#define LDSM_X4_T(r0, r1, r2, r3, addr) \
    asm volatile("ldmatrix.sync.aligned.m8n8.x4.trans.shared.b16 {%0,%1,%2,%3}, [%4];" \
        : "=r"(r0), "=r"(r1), "=r"(r2), "=r"(r3) : "r"(addr))

#define MMA16816(d, a, b0, b1) \
    asm volatile("mma.sync.aligned.m16n8k16.row.col.f32.f16.f16.f32 " \
        "{%0,%1,%2,%3}, {%4,%5,%6,%7}, {%8,%9}, {%0,%1,%2,%3};" \
        : "+f"((d)[0]), "+f"((d)[1]), "+f"((d)[2]), "+f"((d)[3]) \
        : "r"((a)[0]), "r"((a)[1]), "r"((a)[2]), "r"((a)[3]), "r"(b0), "r"(b1))

#define CP_ASYNC16(dst, src, sz) \
    asm volatile("cp.async.cg.shared.global [%0], [%1], 16, %2;" \
        :: "r"(dst), "l"(src), "r"(sz) : "memory")

__device__ __forceinline__ uint32_t pack_h2(h16 a, h16 b) {
    __half2 t = __halves2half2(a, b);
    return *(uint32_t*)&t;
}

// ---------------- tensor-core GEMM via mma.sync (fp16 in, fp32 accum) ----------------
// 3-stage cp.async pipeline, 128x128 tile, 256 threads, 2 CTA/SM.
// modes: 0 = outf = v ; 1 = hres += v ; 2 = gelu(v)->o16 ;
//        3 = patch-embed fused assemble: hres[b*197+t+1] = v + pos
//        5 = cls-row residual: hres[(row*197)*768 + col] += v   (M = 32, N = 768)
#define GSTAGE 32768
#define GSMEM_SZ (3 * GSTAGE)

__global__ void __launch_bounds__(256, 2) gemm_mma_kernel(
    const h16* __restrict__ A, const h16* __restrict__ Bw,
    const float* __restrict__ bias,
    float* __restrict__ outf, float* __restrict__ hres,
    h16* __restrict__ o16, const float* __restrict__ posp,
    int M, int N, int K, int mode)
{
    const uint32_t sbase = smem_u32(dynsmem);
    const int tid = threadIdx.x;
    const int bm = blockIdx.y * 128;
    const int bn = blockIdx.x * 128;
    const int NC = K >> 6;
    const int w = tid >> 5, lane = tid & 31;
    const int wm = w & 3, wn = w >> 2;

    float acc[2][8][4];
#pragma unroll
    for (int mt = 0; mt < 2; mt++)
#pragma unroll
        for (int nt = 0; nt < 8; nt++)
#pragma unroll
            for (int r = 0; r < 4; r++) acc[mt][nt][r] = 0.f;

    auto load_stage = [&](int c, int slot) {
        const uint32_t sb = sbase + (uint32_t)slot * GSTAGE;
        const int k0 = c * 64;
#pragma unroll
        for (int t = 0; t < 2; t++) {
#pragma unroll
            for (int i = 0; i < 4; i++) {
                int s = tid + i * 256;
                int r = s >> 3, seg = s & 7;
                int grow = (t == 0) ? (bm + r) : (bn + r);
                int sz = 16;
                if (t == 0 && grow >= M) { grow = 0; sz = 0; }
                const h16* src = (t == 0 ? A : Bw) + (size_t)grow * K + k0 + seg * 8;
                uint32_t dst = sb + t * 16384 + SW128((uint32_t)(r * 128 + seg * 16));
                CP_ASYNC16(dst, src, sz);
            }
        }
        asm volatile("cp.async.commit_group;" ::: "memory");
    };

    load_stage(0, 0);
    if (NC > 1) load_stage(1, 1);

    int slot = 0;
    for (int c = 0; c < NC; c++) {
        if (c + 1 < NC) {
            asm volatile("cp.async.wait_group 1;" ::: "memory");
        } else {
            asm volatile("cp.async.wait_group 0;" ::: "memory");
        }
        __syncthreads();

        if (c + 2 < NC) {
            int ns = slot + 2;
            if (ns >= 3) ns -= 3;
            load_stage(c + 2, ns);
        }

        const uint32_t sb = sbase + (uint32_t)slot * GSTAGE;
        const uint32_t sa = sb, sbw = sb + 16384;

#pragma unroll
        for (int k16 = 0; k16 < 4; k16++) {
            const int kc = k16 * 16;
            uint32_t Af[2][4];
#pragma unroll
            for (int mt = 0; mt < 2; mt++) {
                uint32_t aoff = SW128((uint32_t)((wm * 32 + mt * 16 + (lane & 15)) * 128
                                                 + (kc + (lane >> 4) * 8) * 2));
                LDSM_X4(Af[mt][0], Af[mt][1], Af[mt][2], Af[mt][3], sa + aoff);
            }
            const int sub = lane >> 3, r8 = lane & 7;
            const int nloc = ((sub & 2) ? 8 : 0) + r8;
            const int kloc = kc + (sub & 1) * 8;
#pragma unroll
            for (int ng = 0; ng < 4; ng++) {
                uint32_t boff = SW128((uint32_t)((wn * 64 + ng * 16 + nloc) * 128 + kloc * 2));
                uint32_t Bf[4];
                LDSM_X4(Bf[0], Bf[1], Bf[2], Bf[3], sbw + boff);
#pragma unroll
                for (int mt = 0; mt < 2; mt++) {
#pragma unroll
                    for (int half = 0; half < 2; half++) {
                        const int nt = ng * 2 + half;
                        MMA16816(acc[mt][nt], Af[mt], Bf[half * 2], Bf[half * 2 + 1]);
                    }
                }
            }
        }

        slot++;
        if (slot >= 3) slot = 0;
    }

    // ---- epilogue ----
#pragma unroll
    for (int mt = 0; mt < 2; mt++) {
        const int r0 = bm + wm * 32 + mt * 16 + (lane >> 2);
#pragma unroll
        for (int nt = 0; nt < 8; nt++) {
            const int col = bn + wn * 64 + nt * 8 + (lane & 3) * 2;
            const float b0 = bias[col], b1 = bias[col + 1];
#pragma unroll
            for (int rr = 0; rr < 2; rr++) {
                const int row = r0 + rr * 8;
                if (row >= M) continue;
                float v0 = acc[mt][nt][rr * 2 + 0] + b0;
                float v1 = acc[mt][nt][rr * 2 + 1] + b1;
                size_t oi = (size_t)row * N + col;
                if (mode == 0) {
                    *(float2*)(outf + oi) = make_float2(v0, v1);
                } else if (mode == 1) {
                    float2* hp = (float2*)(hres + oi);
                    float2 t = *hp;
                    t.x += v0; t.y += v1;
                    *hp = t;
                } else if (mode == 2) {
                    float g0 = 0.5f * v0 * (1.0f + erff(v0 * 0.70710678118654752f));
                    float g1 = 0.5f * v1 * (1.0f + erff(v1 * 0.70710678118654752f));
                    __half2 hv = __floats2half2_rn(g0, g1);
                    *(uint32_t*)(o16 + oi) = *(uint32_t*)&hv;
                } else if (mode == 3) {
                    // patch-embed fused assemble (N == 768)
                    int bb = row / NPATCH;
                    int tt = row - bb * NPATCH;
                    size_t hrow = (size_t)(bb * NTOK + tt + 1);
                    const float* pp = posp + (size_t)(tt + 1) * D_ + col;
                    float2 o = make_float2(v0 + pp[0], v1 + pp[1]);
                    *(float2*)(hres + hrow * D_ + col) = o;
                } else {
                    // mode 5: cls-row residual (N == 768, M == 32)
                    size_t hrow = (size_t)row * NTOK;
                    float2* hp = (float2*)(hres + hrow * D_ + col);
                    float2 t = *hp;
                    t.x += v0; t.y += v1;
                    *hp = t;
                }
            }
        }
    }
}

// ---------------- cls row init: h[b*197] = cls + pos[0] ----------------
__global__ void cls_init_kernel(const float* __restrict__ cls, const float* __restrict__ pos,
                                float* __restrict__ h) {
    int i = blockIdx.x * blockDim.x + threadIdx.x;
    if (i < B_ * D_) {
        int b = i / D_, d = i - b * D_;
        h[(size_t)(b * NTOK) * D_ + d] = cls[d] + pos[d];
    }
}

// ---------------- gather cls rows of o16 into compact buffer ----------------
__global__ void gather_cls_kernel(const h16* __restrict__ o16, h16* __restrict__ oc) {
    int i = blockIdx.x * blockDim.x + threadIdx.x;
    if (i < B_ * D_) {
        int b = i / D_, d = i - b * D_;
        oc[i] = o16[(size_t)(b * NTOK) * D_ + d];
    }
}

// ---------------- batched weight transpose + fp16 (64x64 tile, 128B stores) ----------------
// blockDim (32, 8): 256 threads, tile = 64 n-cols x 64 k-rows
__global__ void wsplit_all_kernel(const float* __restrict__ W, h16* __restrict__ WT,
                                  int K, int N) {
    __shared__ float t[64][65];
    const size_t off = (size_t)blockIdx.z * K * N;
    const float* Wl = W + off;
    h16* WTl = WT + off;
    const int n0 = blockIdx.x * 64, k0 = blockIdx.y * 64;
    const int tid = threadIdx.y * 32 + threadIdx.x;
#pragma unroll
    for (int j = 0; j < 16; j++) {
        int idx = tid + j * 256;
        int kk = idx >> 6, nn = idx & 63;
        t[kk][nn] = Wl[(size_t)(k0 + kk) * N + n0 + nn];
    }
    __syncthreads();
#pragma unroll
    for (int j = 0; j < 8; j++) {
        int idx = tid + j * 256;          // 2048 (n, k-pair) items
        int nn = idx >> 5, kp = idx & 31;
        __half2 hv = __floats2half2_rn(t[2 * kp][nn], t[2 * kp + 1][nn]);
        *(uint32_t*)(WTl + (size_t)(n0 + nn) * K + k0 + 2 * kp) = *(uint32_t*)&hv;
    }
}

__global__ void split_kernel(const float* __restrict__ W, h16* __restrict__ o, int total) {
    for (int i = blockIdx.x * blockDim.x + threadIdx.x; i < total; i += gridDim.x * blockDim.x)
        o[i] = __float2half(W[i]);
}

// ---------------- patch extraction (fp16, float4 vectorized) ----------------
__global__ void extract_patches_kernel(const float* __restrict__ x, h16* __restrict__ p16) {
    const int total = PROWS * D_ / 4;
    for (int i = blockIdx.x * blockDim.x + threadIdx.x; i < total; i += gridDim.x * blockDim.x) {
        int idx = i * 4;
        int row = idx / D_;
        int k   = idx % D_;
        int b   = row / NPATCH;
        int t   = row % NPATCH;
        int ph  = t / 14, pw = t % 14;
        int cin = k >> 8;
        int rem = k & 255;
        int py  = rem >> 4, px = rem & 15;
        size_t src = (((size_t)b * 3 + cin) * 224 + (ph * 16 + py)) * 224 + (pw * 16 + px);
        float4 v = *(const float4*)(x + src);
        __half2 h0 = __floats2half2_rn(v.x, v.y);
        __half2 h1 = __floats2half2_rn(v.z, v.w);
        uint2 u;
        u.x = *(uint32_t*)&h0;
        u.y = *(uint32_t*)&h1;
        *(uint2*)(p16 + idx) = u;
    }
}

// ---------------- LayerNorm (fp32 out, final rows) ----------------
__global__ void ln_kernel(const float* __restrict__ x, const float* __restrict__ w,
                          const float* __restrict__ b, float* __restrict__ y,
                          int D, int inStride, int outStride) {
    const int row = blockIdx.x;
    const float* xr = x + (size_t)row * inStride;
    float* yr = y + (size_t)row * outStride;
    const int tid = threadIdx.x;
    float s = 0.f, q = 0.f;
    for (int i = tid; i < D; i += blockDim.x) { float v = xr[i]; s += v; q += v * v; }
    for (int o = 16; o; o >>= 1) { s += __shfl_xor_sync(~0u, s, o); q += __shfl_xor_sync(~0u, q, o); }
    __shared__ float ss[8], sq[8], mean_s, rstd_s;
    int wid = tid >> 5, lane = tid & 31;
    if (lane == 0) { ss[wid] = s; sq[wid] = q; }
    __syncthreads();
    if (tid == 0) {
        float ts = 0.f, tq = 0.f;
        for (int i = 0; i < (int)(blockDim.x >> 5); i++) { ts += ss[i]; tq += sq[i]; }
        float m = ts / D;
        mean_s = m;
        rstd_s = rsqrtf(tq / D - m * m + 1e-6f);
    }
    __syncthreads();
    float m = mean_s, rs = rstd_s;
    for (int i = tid; i < D; i += blockDim.x)
        yr[i] = (xr[i] - m) * rs * w[i] + b[i];
}

// ---------------- warp-per-row LayerNorm -> fp16 (D=768), strided ----------------
__global__ void __launch_bounds__(256) ln_h_warp_kernel(
    const float* __restrict__ x, const float* __restrict__ wv,
    const float* __restrict__ bv, h16* __restrict__ y16, int rows,
    size_t inStride, size_t outStride)
{
    const int row = blockIdx.x * 8 + (threadIdx.x >> 5);
    if (row >= rows) return;
    const int lane = threadIdx.x & 31;
    const float4* xr = (const float4*)(x + (size_t)row * inStride);
    float4 vals[6];
    float s = 0.f, q = 0.f;
#pragma unroll
    for (int k = 0; k < 6; k++) {
        float4 v = xr[lane + 32 * k];
        vals[k] = v;
        s += v.x + v.y + v.z + v.w;
        q += v.x * v.x + v.y * v.y + v.z * v.z + v.w * v.w;
    }
#pragma unroll
    for (int o = 16; o; o >>= 1) {
        s += __shfl_xor_sync(~0u, s, o);
        q += __shfl_xor_sync(~0u, q, o);
    }
    const float m = s / D_;
    const float rs = rsqrtf(q / D_ - m * m + 1e-6f);
    uint2* yo = (uint2*)(y16 + (size_t)row * outStride);
    const float4* w4 = (const float4*)wv;
    const float4* b4 = (const float4*)bv;
#pragma unroll
    for (int k = 0; k < 6; k++) {
        float4 v = vals[k];
        float4 ww = w4[lane + 32 * k];
        float4 bb = b4[lane + 32 * k];
        __half2 lo = __floats2half2_rn((v.x - m) * rs * ww.x + bb.x,
                                       (v.y - m) * rs * ww.y + bb.y);
        __half2 hi = __floats2half2_rn((v.z - m) * rs * ww.z + bb.z,
                                       (v.w - m) * rs * ww.w + bb.w);
        uint2 u;
        u.x = *(uint32_t*)&lo;
        u.y = *(uint32_t*)&hi;
        yo[lane + 32 * k] = u;
    }
}

// ---------------- attention: HMMA with 3-product hi/lo splits ----------------
#define ASLAB 26624
#define AMMA_SMEM (6 * ASLAB)
__global__ void __launch_bounds__(256) attn_kernel(const float* __restrict__ qkv,
                                                   h16* __restrict__ o16, int ngroups) {
    char* sm = dynsmem;
    const uint32_t sbase = smem_u32(sm);
    const uint32_t Qh = sbase,      Ql = Qh + ASLAB;
    const uint32_t Kh = Ql + ASLAB, Kl = Kh + ASLAB;
    const uint32_t Vh = Kl + ASLAB, Vl = Vh + ASLAB;

    const int bh = blockIdx.x;
    const int b = bh / H_;
    const int h = bh % H_;
    const int tid = threadIdx.x;
    const int lane = tid & 31;
    const int w = tid >> 5;

    for (int idx = tid; idx < 208 * 32; idx += 256) {
        int m = idx >> 5, dp = idx & 31;
        float2 qv = make_float2(0.f, 0.f), kv = qv, vv = qv;
        if (m < NTOK) {
            const float* base = qkv + ((size_t)(b * NTOK + m)) * (3 * D_) + h * DH + dp * 2;
            qv = *(const float2*)(base);
            kv = *(const float2*)(base + D_);
            vv = *(const float2*)(base + 2 * D_);
        }
        uint32_t off = SW128((uint32_t)(m * 128 + dp * 4));
        h16 a0 = __float2half_rn(qv.x), a1 = __float2half_rn(qv.y);
        *(uint32_t*)(sm + (Qh - sbase) + off) = pack_h2(a0, a1);
        *(uint32_t*)(sm + (Ql - sbase) + off) =
            pack_h2(__float2half_rn(qv.x - __half2float(a0)),
                    __float2half_rn(qv.y - __half2float(a1)));
        h16 k0 = __float2half_rn(kv.x), k1 = __float2half_rn(kv.y);
        *(uint32_t*)(sm + (Kh - sbase) + off) = pack_h2(k0, k1);
        *(uint32_t*)(sm + (Kl - sbase) + off) =
            pack_h2(__float2half_rn(kv.x - __half2float(k0)),
                    __float2half_rn(kv.y - __half2float(k1)));
        h16 v0 = __float2half_rn(vv.x), v1 = __float2half_rn(vv.y);
        *(uint32_t*)(sm + (Vh - sbase) + off) = pack_h2(v0, v1);
        *(uint32_t*)(sm + (Vl - sbase) + off) =
            pack_h2(__float2half_rn(vv.x - __half2float(v0)),
                    __float2half_rn(vv.y - __half2float(v1)));
    }
    __syncthreads();

    const int c0 = (lane & 3) * 2;

    for (int mt = w; mt < ngroups; mt += 8) {
        float accS[26][4];
#pragma unroll
        for (int t = 0; t < 26; t++)
#pragma unroll
            for (int i = 0; i < 4; i++) accS[t][i] = 0.f;

#pragma unroll
        for (int kc = 0; kc < 4; kc++) {
            uint32_t Ah4[4], Al4[4];
            {
                uint32_t aoff = SW128((uint32_t)((mt * 16 + (lane & 15)) * 128
                                                 + (kc * 16 + (lane >> 4) * 8) * 2));
                LDSM_X4(Ah4[0], Ah4[1], Ah4[2], Ah4[3], Qh + aoff);
                LDSM_X4(Al4[0], Al4[1], Al4[2], Al4[3], Ql + aoff);
            }
            const int sub = lane >> 3, r8 = lane & 7;
            const int nloc = ((sub & 2) ? 8 : 0) + r8;
            const int kloc = kc * 16 + (sub & 1) * 8;
#pragma unroll
            for (int np = 0; np < 13; np++) {
                uint32_t boff = SW128((uint32_t)((np * 16 + nloc) * 128 + kloc * 2));
                uint32_t BH[4], BL[4];
                LDSM_X4(BH[0], BH[1], BH[2], BH[3], Kh + boff);
                LDSM_X4(BL[0], BL[1], BL[2], BL[3], Kl + boff);
                MMA16816(accS[2 * np], Ah4, BH[0], BH[1]);
                MMA16816(accS[2 * np], Ah4, BL[0], BL[1]);
                MMA16816(accS[2 * np], Al4, BH[0], BH[1]);
                MMA16816(accS[2 * np + 1], Ah4, BH[2], BH[3]);
                MMA16816(accS[2 * np + 1], Ah4, BL[2], BL[3]);
                MMA16816(accS[2 * np + 1], Al4, BH[2], BH[3]);
            }
        }

        float mx0 = -1e30f, mx1 = -1e30f;
#pragma unroll
        for (int t = 0; t < 26; t++) {
#pragma unroll
            for (int i = 0; i < 4; i++) {
                int col = t * 8 + c0 + (i & 1);
                float s = (col < NTOK) ? (accS[t][i] * 0.125f) : -1e30f;
                accS[t][i] = s;
                if (i < 2) mx0 = fmaxf(mx0, s);
                else       mx1 = fmaxf(mx1, s);
            }
        }
        mx0 = fmaxf(mx0, __shfl_xor_sync(~0u, mx0, 1));
        mx0 = fmaxf(mx0, __shfl_xor_sync(~0u, mx0, 2));
        mx1 = fmaxf(mx1, __shfl_xor_sync(~0u, mx1, 1));
        mx1 = fmaxf(mx1, __shfl_xor_sync(~0u, mx1, 2));
        float sum0 = 0.f, sum1 = 0.f;
#pragma unroll
        for (int t = 0; t < 26; t++) {
#pragma unroll
            for (int i = 0; i < 4; i++) {
                float e = expf(accS[t][i] - ((i < 2) ? mx0 : mx1));
                accS[t][i] = e;
                if (i < 2) sum0 += e;
                else       sum1 += e;
            }
        }
        sum0 += __shfl_xor_sync(~0u, sum0, 1);
        sum0 += __shfl_xor_sync(~0u, sum0, 2);
        sum1 += __shfl_xor_sync(~0u, sum1, 1);
        sum1 += __shfl_xor_sync(~0u, sum1, 2);
        const float inv0 = 1.f / sum0, inv1 = 1.f / sum1;

        float accO[8][4];
#pragma unroll
        for (int nt = 0; nt < 8; nt++)
#pragma unroll
            for (int i = 0; i < 4; i++) accO[nt][i] = 0.f;

        const int g = lane >> 3;
        const int vrow_loc = (g & 1) * 8 + (lane & 7);
        const int vcol_b = (g >> 1) * 16;

#pragma unroll
        for (int kk = 0; kk < 13; kk++) {
            float e0 = accS[2 * kk][0] * inv0, e1 = accS[2 * kk][1] * inv0;
            float e2 = accS[2 * kk][2] * inv1, e3 = accS[2 * kk][3] * inv1;
            float f0 = accS[2 * kk + 1][0] * inv0, f1 = accS[2 * kk + 1][1] * inv0;
            float f2 = accS[2 * kk + 1][2] * inv1, f3 = accS[2 * kk + 1][3] * inv1;
            h16 he0 = __float2half_rn(e0), he1 = __float2half_rn(e1);
            h16 he2 = __float2half_rn(e2), he3 = __float2half_rn(e3);
            h16 hf0 = __float2half_rn(f0), hf1 = __float2half_rn(f1);
            h16 hf2 = __float2half_rn(f2), hf3 = __float2half_rn(f3);
            uint32_t aH[4] = { pack_h2(he0, he1), pack_h2(he2, he3),
                               pack_h2(hf0, hf1), pack_h2(hf2, hf3) };
            uint32_t aL[4] = {
                pack_h2(__float2half_rn(e0 - __half2float(he0)), __float2half_rn(e1 - __half2float(he1))),
                pack_h2(__float2half_rn(e2 - __half2float(he2)), __float2half_rn(e3 - __half2float(he3))),
                pack_h2(__float2half_rn(f0 - __half2float(hf0)), __float2half_rn(f1 - __half2float(hf1))),
                pack_h2(__float2half_rn(f2 - __half2float(hf2)), __float2half_rn(f3 - __half2float(hf3))) };

            const int vrow = kk * 16 + vrow_loc;
#pragma unroll
            for (int vg = 0; vg < 4; vg++) {
                uint32_t voff = SW128((uint32_t)(vrow * 128 + vg * 32 + vcol_b));
                uint32_t VH[4], VL[4];
                LDSM_X4_T(VH[0], VH[1], VH[2], VH[3], Vh + voff);
                LDSM_X4_T(VL[0], VL[1], VL[2], VL[3], Vl + voff);
                MMA16816(accO[vg * 2], aH, VH[0], VH[1]);
                MMA16816(accO[vg * 2], aH, VL[0], VL[1]);
                MMA16816(accO[vg * 2], aL, VH[0], VH[1]);
                MMA16816(accO[vg * 2 + 1], aH, VH[2], VH[3]);
                MMA16816(accO[vg * 2 + 1], aH, VL[2], VL[3]);
                MMA16816(accO[vg * 2 + 1], aL, VH[2], VH[3]);
            }
        }

        const int r1 = mt * 16 + (lane >> 2);
        const int r2 = r1 + 8;
#pragma unroll
        for (int nt = 0; nt < 8; nt++) {
            const int col = h * DH + nt * 8 + c0;
            if (r1 < NTOK) {
                __half2 v = __floats2half2_rn(accO[nt][0], accO[nt][1]);
                *(uint32_t*)(o16 + (size_t)(b * NTOK + r1) * D_ + col) = *(uint32_t*)&v;
            }
            if (r2 < NTOK) {
                __half2 v = __floats2half2_rn(accO[nt][2], accO[nt][3]);
                *(uint32_t*)(o16 + (size_t)(b * NTOK + r2) * D_ + col) = *(uint32_t*)&v;
            }
        }
    }
}

// ---------------- host ----------------
extern "C" void kernel_launch(void* const* d_in, const int* in_sizes, int n_in,
                              void* d_out, int out_size) {
    const float* x       = (const float*)d_in[0];
    const float* conv_w  = (const float*)d_in[1];
    const float* conv_b  = (const float*)d_in[2];
    const float* cls_tok = (const float*)d_in[3];
    const float* pos     = (const float*)d_in[4];
    const float* ln1w    = (const float*)d_in[5];
    const float* ln1b    = (const float*)d_in[6];
    const float* qkvw    = (const float*)d_in[7];
    const float* qkvb    = (const float*)d_in[8];
    const float* projw   = (const float*)d_in[9];
    const float* projb   = (const float*)d_in[10];
    const float* ln2w    = (const float*)d_in[11];
    const float* ln2b    = (const float*)d_in[12];
    const float* fc1w    = (const float*)d_in[13];
    const float* fc1b    = (const float*)d_in[14];
    const float* fc2w    = (const float*)d_in[15];
    const float* fc2b    = (const float*)d_in[16];
    const float* lnfw    = (const float*)d_in[17];
    const float* lnfb    = (const float*)d_in[18];

    float *h, *qkv;
    h16 *p16, *cw16, *y16, *o16, *mid16, *oc, *yc;
    h16 *wq, *wp, *w1, *w2;
    cudaGetSymbolAddress((void**)&h,     g_h);
    cudaGetSymbolAddress((void**)&qkv,   g_qkv);
    cudaGetSymbolAddress((void**)&p16,   g_p16);
    cudaGetSymbolAddress((void**)&cw16,  g_cw16);
    cudaGetSymbolAddress((void**)&y16,   g_y16);
    cudaGetSymbolAddress((void**)&o16,   g_o16);
    cudaGetSymbolAddress((void**)&mid16, g_mid16);
    cudaGetSymbolAddress((void**)&oc,    g_oc);
    cudaGetSymbolAddress((void**)&yc,    g_yc);
    cudaGetSymbolAddress((void**)&wq,    g_wqkv);
    cudaGetSymbolAddress((void**)&wp,    g_wproj);
    cudaGetSymbolAddress((void**)&w1,    g_wfc1);
    cudaGetSymbolAddress((void**)&w2,    g_wfc2);

    cudaFuncSetAttribute(attn_kernel, cudaFuncAttributeMaxDynamicSharedMemorySize, AMMA_SMEM);
    cudaFuncSetAttribute(gemm_mma_kernel, cudaFuncAttributeMaxDynamicSharedMemorySize, GSMEM_SZ);

    // ---- weight conversion (transpose + fp16), batched over layers ----
    {
        dim3 blk(32, 8);
        wsplit_all_kernel<<<dim3(3 * D_ / 64, D_ / 64, L_), blk>>>(qkvw, wq, D_, 3 * D_);
        wsplit_all_kernel<<<dim3(D_ / 64, D_ / 64, L_), blk>>>(projw, wp, D_, D_);
        wsplit_all_kernel<<<dim3(F_ / 64, D_ / 64, L_), blk>>>(fc1w, w1, D_, F_);
        wsplit_all_kernel<<<dim3(D_ / 64, F_ / 64, L_), blk>>>(fc2w, w2, F_, D_);
        split_kernel<<<1024, 256>>>(conv_w, cw16, D_ * D_);
    }

    // ---- patch embed: GEMM with fused assemble (mode 3) + cls rows ----
    extract_patches_kernel<<<1024, 256>>>(x, p16);
    cls_init_kernel<<<(B_ * D_ + 255) / 256, 256>>>(cls_tok, pos, h);
    gemm_mma_kernel<<<dim3(D_ / 128, PROWS / 128), 256, GSMEM_SZ>>>(
        p16, cw16, conv_b, nullptr, h, nullptr, pos, PROWS, D_, D_, 3);

    const int mb = (ROWS + 127) / 128;   // 50
    const int lnb = (ROWS + 7) / 8;      // 788
    for (int l = 0; l < L_; l++) {
        const bool last = (l == L_ - 1);

        ln_h_warp_kernel<<<lnb, 256>>>(h, ln1w + l * D_, ln1b + l * D_, y16, ROWS,
                                       (size_t)D_, (size_t)D_);
        gemm_mma_kernel<<<dim3(3 * D_ / 128, mb), 256, GSMEM_SZ>>>(
            y16, wq + (size_t)l * 3 * D_ * D_, qkvb + (size_t)l * 3 * D_,
            qkv, nullptr, nullptr, nullptr, ROWS, 3 * D_, D_, 0);
        attn_kernel<<<B_ * H_, 256, AMMA_SMEM>>>(qkv, o16, last ? 1 : 13);

        if (!last) {
            gemm_mma_kernel<<<dim3(D_ / 128, mb), 256, GSMEM_SZ>>>(
                o16, wp + (size_t)l * D_ * D_, projb + (size_t)l * D_,
                nullptr, h, nullptr, nullptr, ROWS, D_, D_, 1);
            ln_h_warp_kernel<<<lnb, 256>>>(h, ln2w + l * D_, ln2b + l * D_, y16, ROWS,
                                           (size_t)D_, (size_t)D_);
            gemm_mma_kernel<<<dim3(F_ / 128, mb), 256, GSMEM_SZ>>>(
                y16, w1 + (size_t)l * F_ * D_, fc1b + (size_t)l * F_,
                nullptr, nullptr, mid16, nullptr, ROWS, F_, D_, 2);
            gemm_mma_kernel<<<dim3(D_ / 128, mb), 256, GSMEM_SZ>>>(
                mid16, w2 + (size_t)l * D_ * F_, fc2b + (size_t)l * D_,
                nullptr, h, nullptr, nullptr, ROWS, D_, F_, 1);
        } else {
            // last layer: only cls-token rows feed the output
            gather_cls_kernel<<<(B_ * D_ + 255) / 256, 256>>>(o16, oc);
            gemm_mma_kernel<<<dim3(D_ / 128, 1), 256, GSMEM_SZ>>>(
                oc, wp + (size_t)l * D_ * D_, projb + (size_t)l * D_,
                nullptr, h, nullptr, nullptr, B_, D_, D_, 5);
            ln_h_warp_kernel<<<(B_ + 7) / 8, 256>>>(h, ln2w + l * D_, ln2b + l * D_, yc, B_,
                                                    (size_t)NTOK * D_, (size_t)D_);
            gemm_mma_kernel<<<dim3(F_ / 128, 1), 256, GSMEM_SZ>>>(
                yc, w1 + (size_t)l * F_ * D_, fc1b + (size_t)l * F_,
                nullptr, nullptr, mid16, nullptr, B_, F_, D_, 2);
            gemm_mma_kernel<<<dim3(D_ / 128, 1), 256, GSMEM_SZ>>>(
                mid16, w2 + (size_t)l * D_ * F_, fc2b + (size_t)l * D_,
                nullptr, h, nullptr, nullptr, B_, D_, F_, 5);
        }
    }

    ln_kernel<<<B_, 256>>>(h, lnfw, lnfb, (float*)d_out, D_, NTOK * D_, D_);
}

// round 15
// speedup vs baseline: 1.0204x; 1.0047x over previous
#include <cuda_runtime.h>
#include <cuda_fp16.h>
#include <math.h>
#include <stdint.h>

#define B_  32
#define NTOK 197
#define NPATCH 196
#define D_  768
#define H_  12
#define DH  64
#define F_  3072
#define L_  12
#define ROWS  (B_*NTOK)    /* 6304 */
#define PROWS (B_*NPATCH)  /* 6272 */

typedef __half h16;

// single dynamic-shared symbol for the whole TU
extern __shared__ char dynsmem[];

// ---------------- scratch (device globals; no allocation) ----------------
__device__ float g_h[ROWS * D_];
__device__ uint2 g_qx[ROWS * 3 * D_ / 2];   // interleaved {hi-pair, lo-pair} QKV

__device__ h16 g_p16[PROWS * D_];
__device__ h16 g_cw16[D_ * D_];

__device__ h16 g_y16[ROWS * D_];
__device__ h16 g_o16[ROWS * D_];
__device__ h16 g_mid16[ROWS * F_];

__device__ h16 g_oc[B_ * D_];   // compacted cls rows of o16 (last layer)
__device__ h16 g_yc[B_ * D_];   // compacted ln2 output (last layer)

// transposed weights: stored [N][K] per layer
__device__ h16 g_wqkv[L_ * 3 * D_ * D_];
__device__ h16 g_wproj[L_ * D_ * D_];
__device__ h16 g_wfc1[L_ * F_ * D_];
__device__ h16 g_wfc2[L_ * D_ * F_];

// ---------------- helpers ----------------
__device__ __forceinline__ uint32_t smem_u32(const void* p) {
    uint32_t a;
    asm("{ .reg .u64 t; cvta.to.shared.u64 t, %1; cvt.u32.u64 %0, t; }" : "=r"(a) : "l"(p));
    return a;
}
#define SW128(off) ((off) ^ (((off) >> 3) & 0x70))

#define LDSM_X4(r0, r1, r2, r3, addr) \
    asm volatile("ldmatrix.sync.aligned.m8n8.x4.shared.b16 {%0,%1,%2,%3}, [%4];" \
        : "=r"(r0), "=r"(r1), "=r"(r2), "=r"(r3) : "r"(addr))

#define LDSM_X4_T(r0, r1, r2, r3, addr) \
    asm volatile("ldmatrix.sync.aligned.m8n8.x4.trans.shared.b16 {%0,%1,%2,%3}, [%4];" \
        : "=r"(r0), "=r"(r1), "=r"(r2), "=r"(r3) : "r"(addr))

#define MMA16816(d, a, b0, b1) \
    asm volatile("mma.sync.aligned.m16n8k16.row.col.f32.f16.f16.f32 " \
        "{%0,%1,%2,%3}, {%4,%5,%6,%7}, {%8,%9}, {%0,%1,%2,%3};" \
        : "+f"((d)[0]), "+f"((d)[1]), "+f"((d)[2]), "+f"((d)[3]) \
        : "r"((a)[0]), "r"((a)[1]), "r"((a)[2]), "r"((a)[3]), "r"(b0), "r"(b1))

#define CP_ASYNC16(dst, src, sz) \
    asm volatile("cp.async.cg.shared.global [%0], [%1], 16, %2;" \
        :: "r"(dst), "l"(src), "r"(sz) : "memory")

__device__ __forceinline__ uint32_t pack_h2(h16 a, h16 b) {
    __half2 t = __halves2half2(a, b);
    return *(uint32_t*)&t;
}

// ---------------- tensor-core GEMM via mma.sync (fp16 in, fp32 accum) ----------------
// 3-stage cp.async pipeline, 128x128 tile, 256 threads, 2 CTA/SM.
// modes: 0 = outf = v ; 1 = hres += v ; 2 = gelu(v)->o16 ;
//        3 = patch-embed fused assemble: hres[b*197+t+1] = v + pos
//        5 = cls-row residual: hres[(row*197)*768 + col] += v   (M = 32, N = 768)
//        6 = interleaved hi/lo split: ((uint2*)outf)[row*N/2 + col/2] = {hi2, lo2}
#define GSTAGE 32768
#define GSMEM_SZ (3 * GSTAGE)

__global__ void __launch_bounds__(256, 2) gemm_mma_kernel(
    const h16* __restrict__ A, const h16* __restrict__ Bw,
    const float* __restrict__ bias,
    float* __restrict__ outf, float* __restrict__ hres,
    h16* __restrict__ o16, const float* __restrict__ posp,
    int M, int N, int K, int mode)
{
    const uint32_t sbase = smem_u32(dynsmem);
    const int tid = threadIdx.x;
    const int bm = blockIdx.y * 128;
    const int bn = blockIdx.x * 128;
    const int NC = K >> 6;
    const int w = tid >> 5, lane = tid & 31;
    const int wm = w & 3, wn = w >> 2;

    float acc[2][8][4];
#pragma unroll
    for (int mt = 0; mt < 2; mt++)
#pragma unroll
        for (int nt = 0; nt < 8; nt++)
#pragma unroll
            for (int r = 0; r < 4; r++) acc[mt][nt][r] = 0.f;

    auto load_stage = [&](int c, int slot) {
        const uint32_t sb = sbase + (uint32_t)slot * GSTAGE;
        const int k0 = c * 64;
#pragma unroll
        for (int t = 0; t < 2; t++) {
#pragma unroll
            for (int i = 0; i < 4; i++) {
                int s = tid + i * 256;
                int r = s >> 3, seg = s & 7;
                int grow = (t == 0) ? (bm + r) : (bn + r);
                int sz = 16;
                if (t == 0 && grow >= M) { grow = 0; sz = 0; }
                const h16* src = (t == 0 ? A : Bw) + (size_t)grow * K + k0 + seg * 8;
                uint32_t dst = sb + t * 16384 + SW128((uint32_t)(r * 128 + seg * 16));
                CP_ASYNC16(dst, src, sz);
            }
        }
        asm volatile("cp.async.commit_group;" ::: "memory");
    };

    load_stage(0, 0);
    if (NC > 1) load_stage(1, 1);

    int slot = 0;
    for (int c = 0; c < NC; c++) {
        if (c + 1 < NC) {
            asm volatile("cp.async.wait_group 1;" ::: "memory");
        } else {
            asm volatile("cp.async.wait_group 0;" ::: "memory");
        }
        __syncthreads();

        if (c + 2 < NC) {
            int ns = slot + 2;
            if (ns >= 3) ns -= 3;
            load_stage(c + 2, ns);
        }

        const uint32_t sb = sbase + (uint32_t)slot * GSTAGE;
        const uint32_t sa = sb, sbw = sb + 16384;

#pragma unroll
        for (int k16 = 0; k16 < 4; k16++) {
            const int kc = k16 * 16;
            uint32_t Af[2][4];
#pragma unroll
            for (int mt = 0; mt < 2; mt++) {
                uint32_t aoff = SW128((uint32_t)((wm * 32 + mt * 16 + (lane & 15)) * 128
                                                 + (kc + (lane >> 4) * 8) * 2));
                LDSM_X4(Af[mt][0], Af[mt][1], Af[mt][2], Af[mt][3], sa + aoff);
            }
            const int sub = lane >> 3, r8 = lane & 7;
            const int nloc = ((sub & 2) ? 8 : 0) + r8;
            const int kloc = kc + (sub & 1) * 8;
#pragma unroll
            for (int ng = 0; ng < 4; ng++) {
                uint32_t boff = SW128((uint32_t)((wn * 64 + ng * 16 + nloc) * 128 + kloc * 2));
                uint32_t Bf[4];
                LDSM_X4(Bf[0], Bf[1], Bf[2], Bf[3], sbw + boff);
#pragma unroll
                for (int mt = 0; mt < 2; mt++) {
#pragma unroll
                    for (int half = 0; half < 2; half++) {
                        const int nt = ng * 2 + half;
                        MMA16816(acc[mt][nt], Af[mt], Bf[half * 2], Bf[half * 2 + 1]);
                    }
                }
            }
        }

        slot++;
        if (slot >= 3) slot = 0;
    }

    // ---- epilogue ----
#pragma unroll
    for (int mt = 0; mt < 2; mt++) {
        const int r0 = bm + wm * 32 + mt * 16 + (lane >> 2);
#pragma unroll
        for (int nt = 0; nt < 8; nt++) {
            const int col = bn + wn * 64 + nt * 8 + (lane & 3) * 2;
            const float b0 = bias[col], b1 = bias[col + 1];
#pragma unroll
            for (int rr = 0; rr < 2; rr++) {
                const int row = r0 + rr * 8;
                if (row >= M) continue;
                float v0 = acc[mt][nt][rr * 2 + 0] + b0;
                float v1 = acc[mt][nt][rr * 2 + 1] + b1;
                size_t oi = (size_t)row * N + col;
                if (mode == 0) {
                    *(float2*)(outf + oi) = make_float2(v0, v1);
                } else if (mode == 1) {
                    float2* hp = (float2*)(hres + oi);
                    float2 t = *hp;
                    t.x += v0; t.y += v1;
                    *hp = t;
                } else if (mode == 2) {
                    float g0 = 0.5f * v0 * (1.0f + erff(v0 * 0.70710678118654752f));
                    float g1 = 0.5f * v1 * (1.0f + erff(v1 * 0.70710678118654752f));
                    __half2 hv = __floats2half2_rn(g0, g1);
                    *(uint32_t*)(o16 + oi) = *(uint32_t*)&hv;
                } else if (mode == 3) {
                    // patch-embed fused assemble (N == 768)
                    int bb = row / NPATCH;
                    int tt = row - bb * NPATCH;
                    size_t hrow = (size_t)(bb * NTOK + tt + 1);
                    const float* pp = posp + (size_t)(tt + 1) * D_ + col;
                    float2 o = make_float2(v0 + pp[0], v1 + pp[1]);
                    *(float2*)(hres + hrow * D_ + col) = o;
                } else if (mode == 5) {
                    // cls-row residual (N == 768, M == 32)
                    size_t hrow = (size_t)row * NTOK;
                    float2* hp = (float2*)(hres + hrow * D_ + col);
                    float2 t = *hp;
                    t.x += v0; t.y += v1;
                    *hp = t;
                } else {
                    // mode 6: interleaved hi/lo fp16 pair -> single STG.64
                    h16 h0 = __float2half_rn(v0), h1 = __float2half_rn(v1);
                    uint2 u;
                    u.x = pack_h2(h0, h1);
                    u.y = pack_h2(__float2half_rn(v0 - __half2float(h0)),
                                  __float2half_rn(v1 - __half2float(h1)));
                    ((uint2*)outf)[(size_t)row * (N >> 1) + (col >> 1)] = u;
                }
            }
        }
    }
}

// ---------------- cls row init: h[b*197] = cls + pos[0] ----------------
__global__ void cls_init_kernel(const float* __restrict__ cls, const float* __restrict__ pos,
                                float* __restrict__ h) {
    int i = blockIdx.x * blockDim.x + threadIdx.x;
    if (i < B_ * D_) {
        int b = i / D_, d = i - b * D_;
        h[(size_t)(b * NTOK) * D_ + d] = cls[d] + pos[d];
    }
}

// ---------------- gather cls rows of o16 into compact buffer ----------------
__global__ void gather_cls_kernel(const h16* __restrict__ o16, h16* __restrict__ oc) {
    int i = blockIdx.x * blockDim.x + threadIdx.x;
    if (i < B_ * D_) {
        int b = i / D_, d = i - b * D_;
        oc[i] = o16[(size_t)(b * NTOK) * D_ + d];
    }
}

// ---------------- batched weight transpose + fp16 (32n x 64k tile, R12 version) ----------------
__global__ void wsplit_all_kernel(const float* __restrict__ W, h16* __restrict__ WT,
                                  int K, int N) {
    __shared__ float t[64][33];
    const size_t off = (size_t)blockIdx.z * K * N;
    const float* Wl = W + off;
    h16* WTl = WT + off;
    const int n0 = blockIdx.x * 32, k0 = blockIdx.y * 64;
    const int tx = threadIdx.x, ty = threadIdx.y;
#pragma unroll
    for (int j = 0; j < 8; j++) {
        int kk = ty + 8 * j;
        t[kk][tx] = Wl[(size_t)(k0 + kk) * N + n0 + tx];
    }
    __syncthreads();
#pragma unroll
    for (int j = 0; j < 4; j++) {
        int nl = ty + 8 * j;
        int kl = tx * 2;
        __half2 hv = __floats2half2_rn(t[kl][nl], t[kl + 1][nl]);
        *(uint32_t*)(WTl + (size_t)(n0 + nl) * K + k0 + kl) = *(uint32_t*)&hv;
    }
}

__global__ void split_kernel(const float* __restrict__ W, h16* __restrict__ o, int total) {
    for (int i = blockIdx.x * blockDim.x + threadIdx.x; i < total; i += gridDim.x * blockDim.x)
        o[i] = __float2half(W[i]);
}

// ---------------- patch extraction (fp16, float4 vectorized) ----------------
__global__ void extract_patches_kernel(const float* __restrict__ x, h16* __restrict__ p16) {
    const int total = PROWS * D_ / 4;
    for (int i = blockIdx.x * blockDim.x + threadIdx.x; i < total; i += gridDim.x * blockDim.x) {
        int idx = i * 4;
        int row = idx / D_;
        int k   = idx % D_;
        int b   = row / NPATCH;
        int t   = row % NPATCH;
        int ph  = t / 14, pw = t % 14;
        int cin = k >> 8;
        int rem = k & 255;
        int py  = rem >> 4, px = rem & 15;
        size_t src = (((size_t)b * 3 + cin) * 224 + (ph * 16 + py)) * 224 + (pw * 16 + px);
        float4 v = *(const float4*)(x + src);
        __half2 h0 = __floats2half2_rn(v.x, v.y);
        __half2 h1 = __floats2half2_rn(v.z, v.w);
        uint2 u;
        u.x = *(uint32_t*)&h0;
        u.y = *(uint32_t*)&h1;
        *(uint2*)(p16 + idx) = u;
    }
}

// ---------------- LayerNorm (fp32 out, final rows) ----------------
__global__ void ln_kernel(const float* __restrict__ x, const float* __restrict__ w,
                          const float* __restrict__ b, float* __restrict__ y,
                          int D, int inStride, int outStride) {
    const int row = blockIdx.x;
    const float* xr = x + (size_t)row * inStride;
    float* yr = y + (size_t)row * outStride;
    const int tid = threadIdx.x;
    float s = 0.f, q = 0.f;
    for (int i = tid; i < D; i += blockDim.x) { float v = xr[i]; s += v; q += v * v; }
    for (int o = 16; o; o >>= 1) { s += __shfl_xor_sync(~0u, s, o); q += __shfl_xor_sync(~0u, q, o); }
    __shared__ float ss[8], sq[8], mean_s, rstd_s;
    int wid = tid >> 5, lane = tid & 31;
    if (lane == 0) { ss[wid] = s; sq[wid] = q; }
    __syncthreads();
    if (tid == 0) {
        float ts = 0.f, tq = 0.f;
        for (int i = 0; i < (int)(blockDim.x >> 5); i++) { ts += ss[i]; tq += sq[i]; }
        float m = ts / D;
        mean_s = m;
        rstd_s = rsqrtf(tq / D - m * m + 1e-6f);
    }
    __syncthreads();
    float m = mean_s, rs = rstd_s;
    for (int i = tid; i < D; i += blockDim.x)
        yr[i] = (xr[i] - m) * rs * w[i] + b[i];
}

// ---------------- warp-per-row LayerNorm -> fp16 (D=768), strided ----------------
__global__ void __launch_bounds__(256) ln_h_warp_kernel(
    const float* __restrict__ x, const float* __restrict__ wv,
    const float* __restrict__ bv, h16* __restrict__ y16, int rows,
    size_t inStride, size_t outStride)
{
    const int row = blockIdx.x * 8 + (threadIdx.x >> 5);
    if (row >= rows) return;
    const int lane = threadIdx.x & 31;
    const float4* xr = (const float4*)(x + (size_t)row * inStride);
    float4 vals[6];
    float s = 0.f, q = 0.f;
#pragma unroll
    for (int k = 0; k < 6; k++) {
        float4 v = xr[lane + 32 * k];
        vals[k] = v;
        s += v.x + v.y + v.z + v.w;
        q += v.x * v.x + v.y * v.y + v.z * v.z + v.w * v.w;
    }
#pragma unroll
    for (int o = 16; o; o >>= 1) {
        s += __shfl_xor_sync(~0u, s, o);
        q += __shfl_xor_sync(~0u, q, o);
    }
    const float m = s / D_;
    const float rs = rsqrtf(q / D_ - m * m + 1e-6f);
    uint2* yo = (uint2*)(y16 + (size_t)row * outStride);
    const float4* w4 = (const float4*)wv;
    const float4* b4 = (const float4*)bv;
#pragma unroll
    for (int k = 0; k < 6; k++) {
        float4 v = vals[k];
        float4 ww = w4[lane + 32 * k];
        float4 bb = b4[lane + 32 * k];
        __half2 lo = __floats2half2_rn((v.x - m) * rs * ww.x + bb.x,
                                       (v.y - m) * rs * ww.y + bb.y);
        __half2 hi = __floats2half2_rn((v.z - m) * rs * ww.z + bb.z,
                                       (v.w - m) * rs * ww.w + bb.w);
        uint2 u;
        u.x = *(uint32_t*)&lo;
        u.y = *(uint32_t*)&hi;
        yo[lane + 32 * k] = u;
    }
}

// ---------------- attention: HMMA with 3-product hi/lo splits ----------------
// QKV arrives interleaved {hi-pair, lo-pair} -> staging is LDG.64 + 2 STS each.
#define ASLAB 26624
#define AMMA_SMEM (6 * ASLAB)
__global__ void __launch_bounds__(256) attn_kernel(const uint2* __restrict__ qx,
                                                   h16* __restrict__ o16, int ngroups) {
    char* sm = dynsmem;
    const uint32_t sbase = smem_u32(sm);
    const uint32_t Qh = sbase,      Ql = Qh + ASLAB;
    const uint32_t Kh = Ql + ASLAB, Kl = Kh + ASLAB;
    const uint32_t Vh = Kl + ASLAB, Vl = Vh + ASLAB;

    const int bh = blockIdx.x;
    const int b = bh / H_;
    const int h = bh % H_;
    const int tid = threadIdx.x;
    const int lane = tid & 31;
    const int w = tid >> 5;

    // ---- stage: each iteration handles one (m, col-pair) of q, k, v ----
    for (int idx = tid; idx < 208 * 32; idx += 256) {
        int m = idx >> 5, dp = idx & 31;
        uint2 uq = make_uint2(0, 0), uk = uq, uv = uq;
        if (m < NTOK) {
            const uint2* base = qx + (size_t)(b * NTOK + m) * (3 * D_ / 2) + h * 32 + dp;
            uq = base[0];
            uk = base[D_ / 2];
            uv = base[D_];
        }
        uint32_t off = SW128((uint32_t)(m * 128 + dp * 4));
        *(uint32_t*)(sm + (Qh - sbase) + off) = uq.x;
        *(uint32_t*)(sm + (Ql - sbase) + off) = uq.y;
        *(uint32_t*)(sm + (Kh - sbase) + off) = uk.x;
        *(uint32_t*)(sm + (Kl - sbase) + off) = uk.y;
        *(uint32_t*)(sm + (Vh - sbase) + off) = uv.x;
        *(uint32_t*)(sm + (Vl - sbase) + off) = uv.y;
    }
    __syncthreads();

    const int c0 = (lane & 3) * 2;

    for (int mt = w; mt < ngroups; mt += 8) {
        float accS[26][4];
#pragma unroll
        for (int t = 0; t < 26; t++)
#pragma unroll
            for (int i = 0; i < 4; i++) accS[t][i] = 0.f;

#pragma unroll
        for (int kc = 0; kc < 4; kc++) {
            uint32_t Ah4[4], Al4[4];
            {
                uint32_t aoff = SW128((uint32_t)((mt * 16 + (lane & 15)) * 128
                                                 + (kc * 16 + (lane >> 4) * 8) * 2));
                LDSM_X4(Ah4[0], Ah4[1], Ah4[2], Ah4[3], Qh + aoff);
                LDSM_X4(Al4[0], Al4[1], Al4[2], Al4[3], Ql + aoff);
            }
            const int sub = lane >> 3, r8 = lane & 7;
            const int nloc = ((sub & 2) ? 8 : 0) + r8;
            const int kloc = kc * 16 + (sub & 1) * 8;
#pragma unroll
            for (int np = 0; np < 13; np++) {
                uint32_t boff = SW128((uint32_t)((np * 16 + nloc) * 128 + kloc * 2));
                uint32_t BH[4], BL[4];
                LDSM_X4(BH[0], BH[1], BH[2], BH[3], Kh + boff);
                LDSM_X4(BL[0], BL[1], BL[2], BL[3], Kl + boff);
                MMA16816(accS[2 * np], Ah4, BH[0], BH[1]);
                MMA16816(accS[2 * np], Ah4, BL[0], BL[1]);
                MMA16816(accS[2 * np], Al4, BH[0], BH[1]);
                MMA16816(accS[2 * np + 1], Ah4, BH[2], BH[3]);
                MMA16816(accS[2 * np + 1], Ah4, BL[2], BL[3]);
                MMA16816(accS[2 * np + 1], Al4, BH[2], BH[3]);
            }
        }

        float mx0 = -1e30f, mx1 = -1e30f;
#pragma unroll
        for (int t = 0; t < 26; t++) {
#pragma unroll
            for (int i = 0; i < 4; i++) {
                int col = t * 8 + c0 + (i & 1);
                float s = (col < NTOK) ? (accS[t][i] * 0.125f) : -1e30f;
                accS[t][i] = s;
                if (i < 2) mx0 = fmaxf(mx0, s);
                else       mx1 = fmaxf(mx1, s);
            }
        }
        mx0 = fmaxf(mx0, __shfl_xor_sync(~0u, mx0, 1));
        mx0 = fmaxf(mx0, __shfl_xor_sync(~0u, mx0, 2));
        mx1 = fmaxf(mx1, __shfl_xor_sync(~0u, mx1, 1));
        mx1 = fmaxf(mx1, __shfl_xor_sync(~0u, mx1, 2));
        float sum0 = 0.f, sum1 = 0.f;
#pragma unroll
        for (int t = 0; t < 26; t++) {
#pragma unroll
            for (int i = 0; i < 4; i++) {
                float e = expf(accS[t][i] - ((i < 2) ? mx0 : mx1));
                accS[t][i] = e;
                if (i < 2) sum0 += e;
                else       sum1 += e;
            }
        }
        sum0 += __shfl_xor_sync(~0u, sum0, 1);
        sum0 += __shfl_xor_sync(~0u, sum0, 2);
        sum1 += __shfl_xor_sync(~0u, sum1, 1);
        sum1 += __shfl_xor_sync(~0u, sum1, 2);
        const float inv0 = 1.f / sum0, inv1 = 1.f / sum1;

        float accO[8][4];
#pragma unroll
        for (int nt = 0; nt < 8; nt++)
#pragma unroll
            for (int i = 0; i < 4; i++) accO[nt][i] = 0.f;

        const int g = lane >> 3;
        const int vrow_loc = (g & 1) * 8 + (lane & 7);
        const int vcol_b = (g >> 1) * 16;

#pragma unroll
        for (int kk = 0; kk < 13; kk++) {
            float e0 = accS[2 * kk][0] * inv0, e1 = accS[2 * kk][1] * inv0;
            float e2 = accS[2 * kk][2] * inv1, e3 = accS[2 * kk][3] * inv1;
            float f0 = accS[2 * kk + 1][0] * inv0, f1 = accS[2 * kk + 1][1] * inv0;
            float f2 = accS[2 * kk + 1][2] * inv1, f3 = accS[2 * kk + 1][3] * inv1;
            h16 he0 = __float2half_rn(e0), he1 = __float2half_rn(e1);
            h16 he2 = __float2half_rn(e2), he3 = __float2half_rn(e3);
            h16 hf0 = __float2half_rn(f0), hf1 = __float2half_rn(f1);
            h16 hf2 = __float2half_rn(f2), hf3 = __float2half_rn(f3);
            uint32_t aH[4] = { pack_h2(he0, he1), pack_h2(he2, he3),
                               pack_h2(hf0, hf1), pack_h2(hf2, hf3) };
            uint32_t aL[4] = {
                pack_h2(__float2half_rn(e0 - __half2float(he0)), __float2half_rn(e1 - __half2float(he1))),
                pack_h2(__float2half_rn(e2 - __half2float(he2)), __float2half_rn(e3 - __half2float(he3))),
                pack_h2(__float2half_rn(f0 - __half2float(hf0)), __float2half_rn(f1 - __half2float(hf1))),
                pack_h2(__float2half_rn(f2 - __half2float(hf2)), __float2half_rn(f3 - __half2float(hf3))) };

            const int vrow = kk * 16 + vrow_loc;
#pragma unroll
            for (int vg = 0; vg < 4; vg++) {
                uint32_t voff = SW128((uint32_t)(vrow * 128 + vg * 32 + vcol_b));
                uint32_t VH[4], VL[4];
                LDSM_X4_T(VH[0], VH[1], VH[2], VH[3], Vh + voff);
                LDSM_X4_T(VL[0], VL[1], VL[2], VL[3], Vl + voff);
                MMA16816(accO[vg * 2], aH, VH[0], VH[1]);
                MMA16816(accO[vg * 2], aH, VL[0], VL[1]);
                MMA16816(accO[vg * 2], aL, VH[0], VH[1]);
                MMA16816(accO[vg * 2 + 1], aH, VH[2], VH[3]);
                MMA16816(accO[vg * 2 + 1], aH, VL[2], VL[3]);
                MMA16816(accO[vg * 2 + 1], aL, VH[2], VH[3]);
            }
        }

        const int r1 = mt * 16 + (lane >> 2);
        const int r2 = r1 + 8;
#pragma unroll
        for (int nt = 0; nt < 8; nt++) {
            const int col = h * DH + nt * 8 + c0;
            if (r1 < NTOK) {
                __half2 v = __floats2half2_rn(accO[nt][0], accO[nt][1]);
                *(uint32_t*)(o16 + (size_t)(b * NTOK + r1) * D_ + col) = *(uint32_t*)&v;
            }
            if (r2 < NTOK) {
                __half2 v = __floats2half2_rn(accO[nt][2], accO[nt][3]);
                *(uint32_t*)(o16 + (size_t)(b * NTOK + r2) * D_ + col) = *(uint32_t*)&v;
            }
        }
    }
}

// ---------------- host ----------------
extern "C" void kernel_launch(void* const* d_in, const int* in_sizes, int n_in,
                              void* d_out, int out_size) {
    const float* x       = (const float*)d_in[0];
    const float* conv_w  = (const float*)d_in[1];
    const float* conv_b  = (const float*)d_in[2];
    const float* cls_tok = (const float*)d_in[3];
    const float* pos     = (const float*)d_in[4];
    const float* ln1w    = (const float*)d_in[5];
    const float* ln1b    = (const float*)d_in[6];
    const float* qkvw    = (const float*)d_in[7];
    const float* qkvb    = (const float*)d_in[8];
    const float* projw   = (const float*)d_in[9];
    const float* projb   = (const float*)d_in[10];
    const float* ln2w    = (const float*)d_in[11];
    const float* ln2b    = (const float*)d_in[12];
    const float* fc1w    = (const float*)d_in[13];
    const float* fc1b    = (const float*)d_in[14];
    const float* fc2w    = (const float*)d_in[15];
    const float* fc2b    = (const float*)d_in[16];
    const float* lnfw    = (const float*)d_in[17];
    const float* lnfb    = (const float*)d_in[18];

    float *h;
    uint2 *qx;
    h16 *p16, *cw16, *y16, *o16, *mid16, *oc, *yc;
    h16 *wq, *wp, *w1, *w2;
    cudaGetSymbolAddress((void**)&h,     g_h);
    cudaGetSymbolAddress((void**)&qx,    g_qx);
    cudaGetSymbolAddress((void**)&p16,   g_p16);
    cudaGetSymbolAddress((void**)&cw16,  g_cw16);
    cudaGetSymbolAddress((void**)&y16,   g_y16);
    cudaGetSymbolAddress((void**)&o16,   g_o16);
    cudaGetSymbolAddress((void**)&mid16, g_mid16);
    cudaGetSymbolAddress((void**)&oc,    g_oc);
    cudaGetSymbolAddress((void**)&yc,    g_yc);
    cudaGetSymbolAddress((void**)&wq,    g_wqkv);
    cudaGetSymbolAddress((void**)&wp,    g_wproj);
    cudaGetSymbolAddress((void**)&w1,    g_wfc1);
    cudaGetSymbolAddress((void**)&w2,    g_wfc2);

    cudaFuncSetAttribute(attn_kernel, cudaFuncAttributeMaxDynamicSharedMemorySize, AMMA_SMEM);
    cudaFuncSetAttribute(gemm_mma_kernel, cudaFuncAttributeMaxDynamicSharedMemorySize, GSMEM_SZ);

    // ---- weight conversion (transpose + fp16), batched over layers ----
    {
        dim3 blk(32, 8);
        wsplit_all_kernel<<<dim3(3 * D_ / 32, D_ / 64, L_), blk>>>(qkvw, wq, D_, 3 * D_);
        wsplit_all_kernel<<<dim3(D_ / 32, D_ / 64, L_), blk>>>(projw, wp, D_, D_);
        wsplit_all_kernel<<<dim3(F_ / 32, D_ / 64, L_), blk>>>(fc1w, w1, D_, F_);
        wsplit_all_kernel<<<dim3(D_ / 32, F_ / 64, L_), blk>>>(fc2w, w2, F_, D_);
        split_kernel<<<1024, 256>>>(conv_w, cw16, D_ * D_);
    }

    // ---- patch embed: GEMM with fused assemble (mode 3) + cls rows ----
    extract_patches_kernel<<<1024, 256>>>(x, p16);
    cls_init_kernel<<<(B_ * D_ + 255) / 256, 256>>>(cls_tok, pos, h);
    gemm_mma_kernel<<<dim3(D_ / 128, PROWS / 128), 256, GSMEM_SZ>>>(
        p16, cw16, conv_b, nullptr, h, nullptr, pos, PROWS, D_, D_, 3);

    const int mb = (ROWS + 127) / 128;   // 50
    const int lnb = (ROWS + 7) / 8;      // 788
    for (int l = 0; l < L_; l++) {
        const bool last = (l == L_ - 1);

        ln_h_warp_kernel<<<lnb, 256>>>(h, ln1w + l * D_, ln1b + l * D_, y16, ROWS,
                                       (size_t)D_, (size_t)D_);
        gemm_mma_kernel<<<dim3(3 * D_ / 128, mb), 256, GSMEM_SZ>>>(
            y16, wq + (size_t)l * 3 * D_ * D_, qkvb + (size_t)l * 3 * D_,
            (float*)qx, nullptr, nullptr, nullptr, ROWS, 3 * D_, D_, 6);
        attn_kernel<<<B_ * H_, 256, AMMA_SMEM>>>(qx, o16, last ? 1 : 13);

        if (!last) {
            gemm_mma_kernel<<<dim3(D_ / 128, mb), 256, GSMEM_SZ>>>(
                o16, wp + (size_t)l * D_ * D_, projb + (size_t)l * D_,
                nullptr, h, nullptr, nullptr, ROWS, D_, D_, 1);
            ln_h_warp_kernel<<<lnb, 256>>>(h, ln2w + l * D_, ln2b + l * D_, y16, ROWS,
                                           (size_t)D_, (size_t)D_);
            gemm_mma_kernel<<<dim3(F_ / 128, mb), 256, GSMEM_SZ>>>(
                y16, w1 + (size_t)l * F_ * D_, fc1b + (size_t)l * F_,
                nullptr, nullptr, mid16, nullptr, ROWS, F_, D_, 2);
            gemm_mma_kernel<<<dim3(D_ / 128, mb), 256, GSMEM_SZ>>>(
                mid16, w2 + (size_t)l * D_ * F_, fc2b + (size_t)l * D_,
                nullptr, h, nullptr, nullptr, ROWS, D_, F_, 1);
        } else {
            // last layer: only cls-token rows feed the output
            gather_cls_kernel<<<(B_ * D_ + 255) / 256, 256>>>(o16, oc);
            gemm_mma_kernel<<<dim3(D_ / 128, 1), 256, GSMEM_SZ>>>(
                oc, wp + (size_t)l * D_ * D_, projb + (size_t)l * D_,
                nullptr, h, nullptr, nullptr, B_, D_, D_, 5);
            ln_h_warp_kernel<<<(B_ + 7) / 8, 256>>>(h, ln2w + l * D_, ln2b + l * D_, yc, B_,
                                                    (size_t)NTOK * D_, (size_t)D_);
            gemm_mma_kernel<<<dim3(F_ / 128, 1), 256, GSMEM_SZ>>>(
                yc, w1 + (size_t)l * F_ * D_, fc1b + (size_t)l * F_,
                nullptr, nullptr, mid16, nullptr, B_, F_, D_, 2);
            gemm_mma_kernel<<<dim3(D_ / 128, 1), 256, GSMEM_SZ>>>(
                mid16, w2 + (size_t)l * D_ * F_, fc2b + (size_t)l * D_,
                nullptr, h, nullptr, nullptr, B_, D_, F_, 5);
        }
    }

    ln_kernel<<<B_, 256>>>(h, lnfw, lnfb, (float*)d_out, D_, NTOK * D_, D_);
}

// round 16
// speedup vs baseline: 1.0268x; 1.0063x over previous
#include <cuda_runtime.h>
#include <cuda_fp16.h>
#include <math.h>
#include <stdint.h>

#define B_  32
#define NTOK 197
#define NPATCH 196
#define D_  768
#define H_  12
#define DH  64
#define F_  3072
#define L_  12
#define ROWS  (B_*NTOK)    /* 6304 */
#define PROWS (B_*NPATCH)  /* 6272 */

typedef __half h16;

// single dynamic-shared symbol for the whole TU
extern __shared__ char dynsmem[];

// ---------------- scratch (device globals; no allocation) ----------------
__device__ float g_h[ROWS * D_];
__device__ uint2 g_qx[ROWS * 3 * D_ / 2];   // interleaved {hi-pair, lo-pair} QKV

__device__ h16 g_p16[PROWS * D_];
__device__ h16 g_cw16[D_ * D_];

__device__ h16 g_y16[ROWS * D_];
__device__ h16 g_o16[ROWS * D_];
__device__ h16 g_mid16[ROWS * F_];

__device__ h16 g_oc[B_ * D_];   // compacted cls rows of o16 (last layer)
__device__ h16 g_yc[B_ * D_];   // compacted ln2 output (last layer)

// transposed weights: stored [N][K] per layer
__device__ h16 g_wqkv[L_ * 3 * D_ * D_];
__device__ h16 g_wproj[L_ * D_ * D_];
__device__ h16 g_wfc1[L_ * F_ * D_];
__device__ h16 g_wfc2[L_ * D_ * F_];

// ---------------- helpers ----------------
__device__ __forceinline__ uint32_t smem_u32(const void* p) {
    uint32_t a;
    asm("{ .reg .u64 t; cvta.to.shared.u64 t, %1; cvt.u32.u64 %0, t; }" : "=r"(a) : "l"(p));
    return a;
}
#define SW128(off) ((off) ^ (((off) >> 3) & 0x70))

#define LDSM_X4(r0, r1, r2, r3, addr) \
    asm volatile("ldmatrix.sync.aligned.m8n8.x4.shared.b16 {%0,%1,%2,%3}, [%4];" \
        : "=r"(r0), "=r"(r1), "=r"(r2), "=r"(r3) : "r"(addr))

#define LDSM_X4_T(r0, r1, r2, r3, addr) \
    asm volatile("ldmatrix.sync.aligned.m8n8.x4.trans.shared.b16 {%0,%1,%2,%3}, [%4];" \
        : "=r"(r0), "=r"(r1), "=r"(r2), "=r"(r3) : "r"(addr))

#define MMA16816(d, a, b0, b1) \
    asm volatile("mma.sync.aligned.m16n8k16.row.col.f32.f16.f16.f32 " \
        "{%0,%1,%2,%3}, {%4,%5,%6,%7}, {%8,%9}, {%0,%1,%2,%3};" \
        : "+f"((d)[0]), "+f"((d)[1]), "+f"((d)[2]), "+f"((d)[3]) \
        : "r"((a)[0]), "r"((a)[1]), "r"((a)[2]), "r"((a)[3]), "r"(b0), "r"(b1))

#define CP_ASYNC16(dst, src, sz) \
    asm volatile("cp.async.cg.shared.global [%0], [%1], 16, %2;" \
        :: "r"(dst), "l"(src), "r"(sz) : "memory")

__device__ __forceinline__ uint32_t pack_h2(h16 a, h16 b) {
    __half2 t = __halves2half2(a, b);
    return *(uint32_t*)&t;
}

// ---------------- tensor-core GEMM via mma.sync (fp16 in, fp32 accum) ----------------
// 3-stage cp.async pipeline, 128x128 tile, 256 threads, 2 CTA/SM.
// modes: 0 = outf = v ; 1 = hres += v ; 2 = gelu(v)->o16 ;
//        3 = patch-embed fused assemble: hres[b*197+t+1] = v + pos
//        5 = cls-row residual: hres[(row*197)*768 + col] += v   (M = 32, N = 768)
//        6 = interleaved hi/lo split: ((uint2*)outf)[row*N/2 + col/2] = {hi2, lo2}
#define GSTAGE 32768
#define GSMEM_SZ (3 * GSTAGE)

__global__ void __launch_bounds__(256, 2) gemm_mma_kernel(
    const h16* __restrict__ A, const h16* __restrict__ Bw,
    const float* __restrict__ bias,
    float* __restrict__ outf, float* __restrict__ hres,
    h16* __restrict__ o16, const float* __restrict__ posp,
    int M, int N, int K, int mode)
{
    const uint32_t sbase = smem_u32(dynsmem);
    const int tid = threadIdx.x;
    const int bm = blockIdx.y * 128;
    const int bn = blockIdx.x * 128;
    const int NC = K >> 6;
    const int w = tid >> 5, lane = tid & 31;
    const int wm = w & 3, wn = w >> 2;

    float acc[2][8][4];
#pragma unroll
    for (int mt = 0; mt < 2; mt++)
#pragma unroll
        for (int nt = 0; nt < 8; nt++)
#pragma unroll
            for (int r = 0; r < 4; r++) acc[mt][nt][r] = 0.f;

    auto load_stage = [&](int c, int slot) {
        const uint32_t sb = sbase + (uint32_t)slot * GSTAGE;
        const int k0 = c * 64;
#pragma unroll
        for (int t = 0; t < 2; t++) {
#pragma unroll
            for (int i = 0; i < 4; i++) {
                int s = tid + i * 256;
                int r = s >> 3, seg = s & 7;
                int grow = (t == 0) ? (bm + r) : (bn + r);
                int sz = 16;
                if (t == 0 && grow >= M) { grow = 0; sz = 0; }
                const h16* src = (t == 0 ? A : Bw) + (size_t)grow * K + k0 + seg * 8;
                uint32_t dst = sb + t * 16384 + SW128((uint32_t)(r * 128 + seg * 16));
                CP_ASYNC16(dst, src, sz);
            }
        }
        asm volatile("cp.async.commit_group;" ::: "memory");
    };

    load_stage(0, 0);
    if (NC > 1) load_stage(1, 1);

    int slot = 0;
    for (int c = 0; c < NC; c++) {
        if (c + 1 < NC) {
            asm volatile("cp.async.wait_group 1;" ::: "memory");
        } else {
            asm volatile("cp.async.wait_group 0;" ::: "memory");
        }
        __syncthreads();

        if (c + 2 < NC) {
            int ns = slot + 2;
            if (ns >= 3) ns -= 3;
            load_stage(c + 2, ns);
        }

        const uint32_t sb = sbase + (uint32_t)slot * GSTAGE;
        const uint32_t sa = sb, sbw = sb + 16384;

#pragma unroll
        for (int k16 = 0; k16 < 4; k16++) {
            const int kc = k16 * 16;
            uint32_t Af[2][4];
#pragma unroll
            for (int mt = 0; mt < 2; mt++) {
                uint32_t aoff = SW128((uint32_t)((wm * 32 + mt * 16 + (lane & 15)) * 128
                                                 + (kc + (lane >> 4) * 8) * 2));
                LDSM_X4(Af[mt][0], Af[mt][1], Af[mt][2], Af[mt][3], sa + aoff);
            }
            const int sub = lane >> 3, r8 = lane & 7;
            const int nloc = ((sub & 2) ? 8 : 0) + r8;
            const int kloc = kc + (sub & 1) * 8;
#pragma unroll
            for (int ng = 0; ng < 4; ng++) {
                uint32_t boff = SW128((uint32_t)((wn * 64 + ng * 16 + nloc) * 128 + kloc * 2));
                uint32_t Bf[4];
                LDSM_X4(Bf[0], Bf[1], Bf[2], Bf[3], sbw + boff);
#pragma unroll
                for (int mt = 0; mt < 2; mt++) {
#pragma unroll
                    for (int half = 0; half < 2; half++) {
                        const int nt = ng * 2 + half;
                        MMA16816(acc[mt][nt], Af[mt], Bf[half * 2], Bf[half * 2 + 1]);
                    }
                }
            }
        }

        slot++;
        if (slot >= 3) slot = 0;
    }

    // ---- epilogue ----
#pragma unroll
    for (int mt = 0; mt < 2; mt++) {
        const int r0 = bm + wm * 32 + mt * 16 + (lane >> 2);
#pragma unroll
        for (int nt = 0; nt < 8; nt++) {
            const int col = bn + wn * 64 + nt * 8 + (lane & 3) * 2;
            const float b0 = bias[col], b1 = bias[col + 1];
#pragma unroll
            for (int rr = 0; rr < 2; rr++) {
                const int row = r0 + rr * 8;
                if (row >= M) continue;
                float v0 = acc[mt][nt][rr * 2 + 0] + b0;
                float v1 = acc[mt][nt][rr * 2 + 1] + b1;
                size_t oi = (size_t)row * N + col;
                if (mode == 0) {
                    *(float2*)(outf + oi) = make_float2(v0, v1);
                } else if (mode == 1) {
                    float2* hp = (float2*)(hres + oi);
                    float2 t = *hp;
                    t.x += v0; t.y += v1;
                    *hp = t;
                } else if (mode == 2) {
                    float g0 = 0.5f * v0 * (1.0f + erff(v0 * 0.70710678118654752f));
                    float g1 = 0.5f * v1 * (1.0f + erff(v1 * 0.70710678118654752f));
                    __half2 hv = __floats2half2_rn(g0, g1);
                    *(uint32_t*)(o16 + oi) = *(uint32_t*)&hv;
                } else if (mode == 3) {
                    // patch-embed fused assemble (N == 768)
                    int bb = row / NPATCH;
                    int tt = row - bb * NPATCH;
                    size_t hrow = (size_t)(bb * NTOK + tt + 1);
                    const float* pp = posp + (size_t)(tt + 1) * D_ + col;
                    float2 o = make_float2(v0 + pp[0], v1 + pp[1]);
                    *(float2*)(hres + hrow * D_ + col) = o;
                } else if (mode == 5) {
                    // cls-row residual (N == 768, M == 32)
                    size_t hrow = (size_t)row * NTOK;
                    float2* hp = (float2*)(hres + hrow * D_ + col);
                    float2 t = *hp;
                    t.x += v0; t.y += v1;
                    *hp = t;
                } else {
                    // mode 6: interleaved hi/lo fp16 pair -> single STG.64
                    h16 h0 = __float2half_rn(v0), h1 = __float2half_rn(v1);
                    uint2 u;
                    u.x = pack_h2(h0, h1);
                    u.y = pack_h2(__float2half_rn(v0 - __half2float(h0)),
                                  __float2half_rn(v1 - __half2float(h1)));
                    ((uint2*)outf)[(size_t)row * (N >> 1) + (col >> 1)] = u;
                }
            }
        }
    }
}

// ---------------- cls row init: h[b*197] = cls + pos[0] ----------------
__global__ void cls_init_kernel(const float* __restrict__ cls, const float* __restrict__ pos,
                                float* __restrict__ h) {
    int i = blockIdx.x * blockDim.x + threadIdx.x;
    if (i < B_ * D_) {
        int b = i / D_, d = i - b * D_;
        h[(size_t)(b * NTOK) * D_ + d] = cls[d] + pos[d];
    }
}

// ---------------- gather cls rows of o16 into compact buffer ----------------
__global__ void gather_cls_kernel(const h16* __restrict__ o16, h16* __restrict__ oc) {
    int i = blockIdx.x * blockDim.x + threadIdx.x;
    if (i < B_ * D_) {
        int b = i / D_, d = i - b * D_;
        oc[i] = o16[(size_t)(b * NTOK) * D_ + d];
    }
}

// ---------------- batched weight transpose + fp16 (32n x 64k tile) ----------------
__global__ void wsplit_all_kernel(const float* __restrict__ W, h16* __restrict__ WT,
                                  int K, int N) {
    __shared__ float t[64][33];
    const size_t off = (size_t)blockIdx.z * K * N;
    const float* Wl = W + off;
    h16* WTl = WT + off;
    const int n0 = blockIdx.x * 32, k0 = blockIdx.y * 64;
    const int tx = threadIdx.x, ty = threadIdx.y;
#pragma unroll
    for (int j = 0; j < 8; j++) {
        int kk = ty + 8 * j;
        t[kk][tx] = Wl[(size_t)(k0 + kk) * N + n0 + tx];
    }
    __syncthreads();
#pragma unroll
    for (int j = 0; j < 4; j++) {
        int nl = ty + 8 * j;
        int kl = tx * 2;
        __half2 hv = __floats2half2_rn(t[kl][nl], t[kl + 1][nl]);
        *(uint32_t*)(WTl + (size_t)(n0 + nl) * K + k0 + kl) = *(uint32_t*)&hv;
    }
}

__global__ void split_kernel(const float* __restrict__ W, h16* __restrict__ o, int total) {
    for (int i = blockIdx.x * blockDim.x + threadIdx.x; i < total; i += gridDim.x * blockDim.x)
        o[i] = __float2half(W[i]);
}

// ---------------- patch extraction (fp16, float4 vectorized) ----------------
__global__ void extract_patches_kernel(const float* __restrict__ x, h16* __restrict__ p16) {
    const int total = PROWS * D_ / 4;
    for (int i = blockIdx.x * blockDim.x + threadIdx.x; i < total; i += gridDim.x * blockDim.x) {
        int idx = i * 4;
        int row = idx / D_;
        int k   = idx % D_;
        int b   = row / NPATCH;
        int t   = row % NPATCH;
        int ph  = t / 14, pw = t % 14;
        int cin = k >> 8;
        int rem = k & 255;
        int py  = rem >> 4, px = rem & 15;
        size_t src = (((size_t)b * 3 + cin) * 224 + (ph * 16 + py)) * 224 + (pw * 16 + px);
        float4 v = *(const float4*)(x + src);
        __half2 h0 = __floats2half2_rn(v.x, v.y);
        __half2 h1 = __floats2half2_rn(v.z, v.w);
        uint2 u;
        u.x = *(uint32_t*)&h0;
        u.y = *(uint32_t*)&h1;
        *(uint2*)(p16 + idx) = u;
    }
}

// ---------------- LayerNorm (fp32 out, final rows) ----------------
__global__ void ln_kernel(const float* __restrict__ x, const float* __restrict__ w,
                          const float* __restrict__ b, float* __restrict__ y,
                          int D, int inStride, int outStride) {
    const int row = blockIdx.x;
    const float* xr = x + (size_t)row * inStride;
    float* yr = y + (size_t)row * outStride;
    const int tid = threadIdx.x;
    float s = 0.f, q = 0.f;
    for (int i = tid; i < D; i += blockDim.x) { float v = xr[i]; s += v; q += v * v; }
    for (int o = 16; o; o >>= 1) { s += __shfl_xor_sync(~0u, s, o); q += __shfl_xor_sync(~0u, q, o); }
    __shared__ float ss[8], sq[8], mean_s, rstd_s;
    int wid = tid >> 5, lane = tid & 31;
    if (lane == 0) { ss[wid] = s; sq[wid] = q; }
    __syncthreads();
    if (tid == 0) {
        float ts = 0.f, tq = 0.f;
        for (int i = 0; i < (int)(blockDim.x >> 5); i++) { ts += ss[i]; tq += sq[i]; }
        float m = ts / D;
        mean_s = m;
        rstd_s = rsqrtf(tq / D - m * m + 1e-6f);
    }
    __syncthreads();
    float m = mean_s, rs = rstd_s;
    for (int i = tid; i < D; i += blockDim.x)
        yr[i] = (xr[i] - m) * rs * w[i] + b[i];
}

// ---------------- warp-per-row LayerNorm -> fp16 (D=768), strided ----------------
__global__ void __launch_bounds__(256) ln_h_warp_kernel(
    const float* __restrict__ x, const float* __restrict__ wv,
    const float* __restrict__ bv, h16* __restrict__ y16, int rows,
    size_t inStride, size_t outStride)
{
    const int row = blockIdx.x * 8 + (threadIdx.x >> 5);
    if (row >= rows) return;
    const int lane = threadIdx.x & 31;
    const float4* xr = (const float4*)(x + (size_t)row * inStride);
    float4 vals[6];
    float s = 0.f, q = 0.f;
#pragma unroll
    for (int k = 0; k < 6; k++) {
        float4 v = xr[lane + 32 * k];
        vals[k] = v;
        s += v.x + v.y + v.z + v.w;
        q += v.x * v.x + v.y * v.y + v.z * v.z + v.w * v.w;
    }
#pragma unroll
    for (int o = 16; o; o >>= 1) {
        s += __shfl_xor_sync(~0u, s, o);
        q += __shfl_xor_sync(~0u, q, o);
    }
    const float m = s / D_;
    const float rs = rsqrtf(q / D_ - m * m + 1e-6f);
    uint2* yo = (uint2*)(y16 + (size_t)row * outStride);
    const float4* w4 = (const float4*)wv;
    const float4* b4 = (const float4*)bv;
#pragma unroll
    for (int k = 0; k < 6; k++) {
        float4 v = vals[k];
        float4 ww = w4[lane + 32 * k];
        float4 bb = b4[lane + 32 * k];
        __half2 lo = __floats2half2_rn((v.x - m) * rs * ww.x + bb.x,
                                       (v.y - m) * rs * ww.y + bb.y);
        __half2 hi = __floats2half2_rn((v.z - m) * rs * ww.z + bb.z,
                                       (v.w - m) * rs * ww.w + bb.w);
        uint2 u;
        u.x = *(uint32_t*)&lo;
        u.y = *(uint32_t*)&hi;
        yo[lane + 32 * k] = u;
    }
}

// ---------------- attention: HMMA with 3-product hi/lo splits ----------------
#define ASLAB 26624
#define AMMA_SMEM (6 * ASLAB)
__global__ void __launch_bounds__(256) attn_kernel(const uint2* __restrict__ qx,
                                                   h16* __restrict__ o16, int ngroups) {
    char* sm = dynsmem;
    const uint32_t sbase = smem_u32(sm);
    const uint32_t Qh = sbase,      Ql = Qh + ASLAB;
    const uint32_t Kh = Ql + ASLAB, Kl = Kh + ASLAB;
    const uint32_t Vh = Kl + ASLAB, Vl = Vh + ASLAB;

    const int bh = blockIdx.x;
    const int b = bh / H_;
    const int h = bh % H_;
    const int tid = threadIdx.x;
    const int lane = tid & 31;
    const int w = tid >> 5;

    for (int idx = tid; idx < 208 * 32; idx += 256) {
        int m = idx >> 5, dp = idx & 31;
        uint2 uq = make_uint2(0, 0), uk = uq, uv = uq;
        if (m < NTOK) {
            const uint2* base = qx + (size_t)(b * NTOK + m) * (3 * D_ / 2) + h * 32 + dp;
            uq = base[0];
            uk = base[D_ / 2];
            uv = base[D_];
        }
        uint32_t off = SW128((uint32_t)(m * 128 + dp * 4));
        *(uint32_t*)(sm + (Qh - sbase) + off) = uq.x;
        *(uint32_t*)(sm + (Ql - sbase) + off) = uq.y;
        *(uint32_t*)(sm + (Kh - sbase) + off) = uk.x;
        *(uint32_t*)(sm + (Kl - sbase) + off) = uk.y;
        *(uint32_t*)(sm + (Vh - sbase) + off) = uv.x;
        *(uint32_t*)(sm + (Vl - sbase) + off) = uv.y;
    }
    __syncthreads();

    const int c0 = (lane & 3) * 2;

    for (int mt = w; mt < ngroups; mt += 8) {
        float accS[26][4];
#pragma unroll
        for (int t = 0; t < 26; t++)
#pragma unroll
            for (int i = 0; i < 4; i++) accS[t][i] = 0.f;

#pragma unroll
        for (int kc = 0; kc < 4; kc++) {
            uint32_t Ah4[4], Al4[4];
            {
                uint32_t aoff = SW128((uint32_t)((mt * 16 + (lane & 15)) * 128
                                                 + (kc * 16 + (lane >> 4) * 8) * 2));
                LDSM_X4(Ah4[0], Ah4[1], Ah4[2], Ah4[3], Qh + aoff);
                LDSM_X4(Al4[0], Al4[1], Al4[2], Al4[3], Ql + aoff);
            }
            const int sub = lane >> 3, r8 = lane & 7;
            const int nloc = ((sub & 2) ? 8 : 0) + r8;
            const int kloc = kc * 16 + (sub & 1) * 8;
#pragma unroll
            for (int np = 0; np < 13; np++) {
                uint32_t boff = SW128((uint32_t)((np * 16 + nloc) * 128 + kloc * 2));
                uint32_t BH[4], BL[4];
                LDSM_X4(BH[0], BH[1], BH[2], BH[3], Kh + boff);
                LDSM_X4(BL[0], BL[1], BL[2], BL[3], Kl + boff);
                MMA16816(accS[2 * np], Ah4, BH[0], BH[1]);
                MMA16816(accS[2 * np], Ah4, BL[0], BL[1]);
                MMA16816(accS[2 * np], Al4, BH[0], BH[1]);
                MMA16816(accS[2 * np + 1], Ah4, BH[2], BH[3]);
                MMA16816(accS[2 * np + 1], Ah4, BL[2], BL[3]);
                MMA16816(accS[2 * np + 1], Al4, BH[2], BH[3]);
            }
        }

        float mx0 = -1e30f, mx1 = -1e30f;
#pragma unroll
        for (int t = 0; t < 26; t++) {
#pragma unroll
            for (int i = 0; i < 4; i++) {
                int col = t * 8 + c0 + (i & 1);
                float s = (col < NTOK) ? (accS[t][i] * 0.125f) : -1e30f;
                accS[t][i] = s;
                if (i < 2) mx0 = fmaxf(mx0, s);
                else       mx1 = fmaxf(mx1, s);
            }
        }
        mx0 = fmaxf(mx0, __shfl_xor_sync(~0u, mx0, 1));
        mx0 = fmaxf(mx0, __shfl_xor_sync(~0u, mx0, 2));
        mx1 = fmaxf(mx1, __shfl_xor_sync(~0u, mx1, 1));
        mx1 = fmaxf(mx1, __shfl_xor_sync(~0u, mx1, 2));
        float sum0 = 0.f, sum1 = 0.f;
#pragma unroll
        for (int t = 0; t < 26; t++) {
#pragma unroll
            for (int i = 0; i < 4; i++) {
                float e = expf(accS[t][i] - ((i < 2) ? mx0 : mx1));
                accS[t][i] = e;
                if (i < 2) sum0 += e;
                else       sum1 += e;
            }
        }
        sum0 += __shfl_xor_sync(~0u, sum0, 1);
        sum0 += __shfl_xor_sync(~0u, sum0, 2);
        sum1 += __shfl_xor_sync(~0u, sum1, 1);
        sum1 += __shfl_xor_sync(~0u, sum1, 2);
        const float inv0 = 1.f / sum0, inv1 = 1.f / sum1;

        float accO[8][4];
#pragma unroll
        for (int nt = 0; nt < 8; nt++)
#pragma unroll
            for (int i = 0; i < 4; i++) accO[nt][i] = 0.f;

        const int g = lane >> 3;
        const int vrow_loc = (g & 1) * 8 + (lane & 7);
        const int vcol_b = (g >> 1) * 16;

#pragma unroll
        for (int kk = 0; kk < 13; kk++) {
            float e0 = accS[2 * kk][0] * inv0, e1 = accS[2 * kk][1] * inv0;
            float e2 = accS[2 * kk][2] * inv1, e3 = accS[2 * kk][3] * inv1;
            float f0 = accS[2 * kk + 1][0] * inv0, f1 = accS[2 * kk + 1][1] * inv0;
            float f2 = accS[2 * kk + 1][2] * inv1, f3 = accS[2 * kk + 1][3] * inv1;
            h16 he0 = __float2half_rn(e0), he1 = __float2half_rn(e1);
            h16 he2 = __float2half_rn(e2), he3 = __float2half_rn(e3);
            h16 hf0 = __float2half_rn(f0), hf1 = __float2half_rn(f1);
            h16 hf2 = __float2half_rn(f2), hf3 = __float2half_rn(f3);
            uint32_t aH[4] = { pack_h2(he0, he1), pack_h2(he2, he3),
                               pack_h2(hf0, hf1), pack_h2(hf2, hf3) };
            uint32_t aL[4] = {
                pack_h2(__float2half_rn(e0 - __half2float(he0)), __float2half_rn(e1 - __half2float(he1))),
                pack_h2(__float2half_rn(e2 - __half2float(he2)), __float2half_rn(e3 - __half2float(he3))),
                pack_h2(__float2half_rn(f0 - __half2float(hf0)), __float2half_rn(f1 - __half2float(hf1))),
                pack_h2(__float2half_rn(f2 - __half2float(hf2)), __float2half_rn(f3 - __half2float(hf3))) };

            const int vrow = kk * 16 + vrow_loc;
#pragma unroll
            for (int vg = 0; vg < 4; vg++) {
                uint32_t voff = SW128((uint32_t)(vrow * 128 + vg * 32 + vcol_b));
                uint32_t VH[4], VL[4];
                LDSM_X4_T(VH[0], VH[1], VH[2], VH[3], Vh + voff);
                LDSM_X4_T(VL[0], VL[1], VL[2], VL[3], Vl + voff);
                MMA16816(accO[vg * 2], aH, VH[0], VH[1]);
                MMA16816(accO[vg * 2], aH, VL[0], VL[1]);
                MMA16816(accO[vg * 2], aL, VH[0], VH[1]);
                MMA16816(accO[vg * 2 + 1], aH, VH[2], VH[3]);
                MMA16816(accO[vg * 2 + 1], aH, VL[2], VL[3]);
                MMA16816(accO[vg * 2 + 1], aL, VH[2], VH[3]);
            }
        }

        const int r1 = mt * 16 + (lane >> 2);
        const int r2 = r1 + 8;
#pragma unroll
        for (int nt = 0; nt < 8; nt++) {
            const int col = h * DH + nt * 8 + c0;
            if (r1 < NTOK) {
                __half2 v = __floats2half2_rn(accO[nt][0], accO[nt][1]);
                *(uint32_t*)(o16 + (size_t)(b * NTOK + r1) * D_ + col) = *(uint32_t*)&v;
            }
            if (r2 < NTOK) {
                __half2 v = __floats2half2_rn(accO[nt][2], accO[nt][3]);
                *(uint32_t*)(o16 + (size_t)(b * NTOK + r2) * D_ + col) = *(uint32_t*)&v;
            }
        }
    }
}

// ---------------- host ----------------
extern "C" void kernel_launch(void* const* d_in, const int* in_sizes, int n_in,
                              void* d_out, int out_size) {
    const float* x       = (const float*)d_in[0];
    const float* conv_w  = (const float*)d_in[1];
    const float* conv_b  = (const float*)d_in[2];
    const float* cls_tok = (const float*)d_in[3];
    const float* pos     = (const float*)d_in[4];
    const float* ln1w    = (const float*)d_in[5];
    const float* ln1b    = (const float*)d_in[6];
    const float* qkvw    = (const float*)d_in[7];
    const float* qkvb    = (const float*)d_in[8];
    const float* projw   = (const float*)d_in[9];
    const float* projb   = (const float*)d_in[10];
    const float* ln2w    = (const float*)d_in[11];
    const float* ln2b    = (const float*)d_in[12];
    const float* fc1w    = (const float*)d_in[13];
    const float* fc1b    = (const float*)d_in[14];
    const float* fc2w    = (const float*)d_in[15];
    const float* fc2b    = (const float*)d_in[16];
    const float* lnfw    = (const float*)d_in[17];
    const float* lnfb    = (const float*)d_in[18];

    float *h;
    uint2 *qx;
    h16 *p16, *cw16, *y16, *o16, *mid16, *oc, *yc;
    h16 *wq, *wp, *w1, *w2;
    cudaGetSymbolAddress((void**)&h,     g_h);
    cudaGetSymbolAddress((void**)&qx,    g_qx);
    cudaGetSymbolAddress((void**)&p16,   g_p16);
    cudaGetSymbolAddress((void**)&cw16,  g_cw16);
    cudaGetSymbolAddress((void**)&y16,   g_y16);
    cudaGetSymbolAddress((void**)&o16,   g_o16);
    cudaGetSymbolAddress((void**)&mid16, g_mid16);
    cudaGetSymbolAddress((void**)&oc,    g_oc);
    cudaGetSymbolAddress((void**)&yc,    g_yc);
    cudaGetSymbolAddress((void**)&wq,    g_wqkv);
    cudaGetSymbolAddress((void**)&wp,    g_wproj);
    cudaGetSymbolAddress((void**)&w1,    g_wfc1);
    cudaGetSymbolAddress((void**)&w2,    g_wfc2);

    cudaFuncSetAttribute(attn_kernel, cudaFuncAttributeMaxDynamicSharedMemorySize, AMMA_SMEM);
    cudaFuncSetAttribute(gemm_mma_kernel, cudaFuncAttributeMaxDynamicSharedMemorySize, GSMEM_SZ);

    // ---- fork: weight conversion on a side stream, overlapped with patch embed ----
    cudaStream_t s2;
    cudaEvent_t evFork, evJoin;
    cudaStreamCreateWithFlags(&s2, cudaStreamNonBlocking);
    cudaEventCreateWithFlags(&evFork, cudaEventDisableTiming);
    cudaEventCreateWithFlags(&evJoin, cudaEventDisableTiming);

    cudaEventRecord(evFork, 0);
    cudaStreamWaitEvent(s2, evFork, 0);
    {
        dim3 blk(32, 8);
        wsplit_all_kernel<<<dim3(3 * D_ / 32, D_ / 64, L_), blk, 0, s2>>>(qkvw, wq, D_, 3 * D_);
        wsplit_all_kernel<<<dim3(D_ / 32, D_ / 64, L_), blk, 0, s2>>>(projw, wp, D_, D_);
        wsplit_all_kernel<<<dim3(F_ / 32, D_ / 64, L_), blk, 0, s2>>>(fc1w, w1, D_, F_);
        wsplit_all_kernel<<<dim3(D_ / 32, F_ / 64, L_), blk, 0, s2>>>(fc2w, w2, F_, D_);
    }
    cudaEventRecord(evJoin, s2);

    // ---- patch embed on the main stream (independent of wq/wp/w1/w2) ----
    split_kernel<<<1024, 256>>>(conv_w, cw16, D_ * D_);
    extract_patches_kernel<<<1024, 256>>>(x, p16);
    cls_init_kernel<<<(B_ * D_ + 255) / 256, 256>>>(cls_tok, pos, h);
    gemm_mma_kernel<<<dim3(D_ / 128, PROWS / 128), 256, GSMEM_SZ>>>(
        p16, cw16, conv_b, nullptr, h, nullptr, pos, PROWS, D_, D_, 3);

    // join: everything after needs the converted weights
    cudaStreamWaitEvent(0, evJoin, 0);

    const int mb = (ROWS + 127) / 128;   // 50
    const int lnb = (ROWS + 7) / 8;      // 788
    for (int l = 0; l < L_; l++) {
        const bool last = (l == L_ - 1);

        ln_h_warp_kernel<<<lnb, 256>>>(h, ln1w + l * D_, ln1b + l * D_, y16, ROWS,
                                       (size_t)D_, (size_t)D_);
        gemm_mma_kernel<<<dim3(3 * D_ / 128, mb), 256, GSMEM_SZ>>>(
            y16, wq + (size_t)l * 3 * D_ * D_, qkvb + (size_t)l * 3 * D_,
            (float*)qx, nullptr, nullptr, nullptr, ROWS, 3 * D_, D_, 6);
        attn_kernel<<<B_ * H_, 256, AMMA_SMEM>>>(qx, o16, last ? 1 : 13);

        if (!last) {
            gemm_mma_kernel<<<dim3(D_ / 128, mb), 256, GSMEM_SZ>>>(
                o16, wp + (size_t)l * D_ * D_, projb + (size_t)l * D_,
                nullptr, h, nullptr, nullptr, ROWS, D_, D_, 1);
            ln_h_warp_kernel<<<lnb, 256>>>(h, ln2w + l * D_, ln2b + l * D_, y16, ROWS,
                                           (size_t)D_, (size_t)D_);
            gemm_mma_kernel<<<dim3(F_ / 128, mb), 256, GSMEM_SZ>>>(
                y16, w1 + (size_t)l * F_ * D_, fc1b + (size_t)l * F_,
                nullptr, nullptr, mid16, nullptr, ROWS, F_, D_, 2);
            gemm_mma_kernel<<<dim3(D_ / 128, mb), 256, GSMEM_SZ>>>(
                mid16, w2 + (size_t)l * D_ * F_, fc2b + (size_t)l * D_,
                nullptr, h, nullptr, nullptr, ROWS, D_, F_, 1);
        } else {
            // last layer: only cls-token rows feed the output
            gather_cls_kernel<<<(B_ * D_ + 255) / 256, 256>>>(o16, oc);
            gemm_mma_kernel<<<dim3(D_ / 128, 1), 256, GSMEM_SZ>>>(
                oc, wp + (size_t)l * D_ * D_, projb + (size_t)l * D_,
                nullptr, h, nullptr, nullptr, B_, D_, D_, 5);
            ln_h_warp_kernel<<<(B_ + 7) / 8, 256>>>(h, ln2w + l * D_, ln2b + l * D_, yc, B_,
                                                    (size_t)NTOK * D_, (size_t)D_);
            gemm_mma_kernel<<<dim3(F_ / 128, 1), 256, GSMEM_SZ>>>(
                yc, w1 + (size_t)l * F_ * D_, fc1b + (size_t)l * F_,
                nullptr, nullptr, mid16, nullptr, B_, F_, D_, 2);
            gemm_mma_kernel<<<dim3(D_ / 128, 1), 256, GSMEM_SZ>>>(
                mid16, w2 + (size_t)l * D_ * F_, fc2b + (size_t)l * D_,
                nullptr, h, nullptr, nullptr, B_, D_, F_, 5);
        }
    }

    ln_kernel<<<B_, 256>>>(h, lnfw, lnfb, (float*)d_out, D_, NTOK * D_, D_);
}

// round 17
// speedup vs baseline: 1.0383x; 1.0112x over previous
#include <cuda_runtime.h>
#include <cuda_fp16.h>
#include <math.h>
#include <stdint.h>

#define B_  32
#define NTOK 197
#define NPATCH 196
#define D_  768
#define H_  12
#define DH  64
#define F_  3072
#define L_  12
#define ROWS  (B_*NTOK)    /* 6304 */
#define PROWS (B_*NPATCH)  /* 6272 */

typedef __half h16;

// single dynamic-shared symbol for the whole TU
extern __shared__ char dynsmem[];

// ---------------- scratch (device globals; no allocation) ----------------
__device__ float g_h[ROWS * D_];
__device__ uint2 g_qx[ROWS * 3 * D_ / 2];   // interleaved {hi-pair, lo-pair} QKV

__device__ h16 g_p16[PROWS * D_];
__device__ h16 g_cw16[D_ * D_];

__device__ h16 g_y16[ROWS * D_];
__device__ h16 g_o16[ROWS * D_];
__device__ h16 g_mid16[ROWS * F_];

__device__ h16 g_oc[B_ * D_];   // compacted cls rows of o16 (last layer)
__device__ h16 g_yc[B_ * D_];   // compacted ln2 output (last layer)

// transposed weights: stored [N][K] per layer
__device__ h16 g_wqkv[L_ * 3 * D_ * D_];
__device__ h16 g_wproj[L_ * D_ * D_];
__device__ h16 g_wfc1[L_ * F_ * D_];
__device__ h16 g_wfc2[L_ * D_ * F_];

// ---------------- helpers ----------------
__device__ __forceinline__ uint32_t smem_u32(const void* p) {
    uint32_t a;
    asm("{ .reg .u64 t; cvta.to.shared.u64 t, %1; cvt.u32.u64 %0, t; }" : "=r"(a) : "l"(p));
    return a;
}
#define SW128(off) ((off) ^ (((off) >> 3) & 0x70))

#define LDSM_X4(r0, r1, r2, r3, addr) \
    asm volatile("ldmatrix.sync.aligned.m8n8.x4.shared.b16 {%0,%1,%2,%3}, [%4];" \
        : "=r"(r0), "=r"(r1), "=r"(r2), "=r"(r3) : "r"(addr))

#define LDSM_X4_T(r0, r1, r2, r3, addr) \
    asm volatile("ldmatrix.sync.aligned.m8n8.x4.trans.shared.b16 {%0,%1,%2,%3}, [%4];" \
        : "=r"(r0), "=r"(r1), "=r"(r2), "=r"(r3) : "r"(addr))

#define MMA16816(d, a, b0, b1) \
    asm volatile("mma.sync.aligned.m16n8k16.row.col.f32.f16.f16.f32 " \
        "{%0,%1,%2,%3}, {%4,%5,%6,%7}, {%8,%9}, {%0,%1,%2,%3};" \
        : "+f"((d)[0]), "+f"((d)[1]), "+f"((d)[2]), "+f"((d)[3]) \
        : "r"((a)[0]), "r"((a)[1]), "r"((a)[2]), "r"((a)[3]), "r"(b0), "r"(b1))

#define CP_ASYNC16(dst, src, sz) \
    asm volatile("cp.async.cg.shared.global [%0], [%1], 16, %2;" \
        :: "r"(dst), "l"(src), "r"(sz) : "memory")

__device__ __forceinline__ uint32_t pack_h2(h16 a, h16 b) {
    __half2 t = __halves2half2(a, b);
    return *(uint32_t*)&t;
}

// ---------------- tensor-core GEMM via mma.sync (fp16 in, fp32 accum) ----------------
// 3-stage cp.async pipeline, 128x128 tile, 256 threads, 2 CTA/SM.
// modes: 0 = outf = v ; 1 = hres += v ; 2 = gelu(v)->o16 ;
//        3 = patch-embed fused assemble: hres[b*197+t+1] = v + pos
//        5 = cls-row residual: hres[(row*197)*768 + col] += v   (M = 32, N = 768)
//        6 = interleaved hi/lo split: ((uint2*)outf)[row*N/2 + col/2] = {hi2, lo2}
#define GSTAGE 32768
#define GSMEM_SZ (3 * GSTAGE)

__global__ void __launch_bounds__(256, 2) gemm_mma_kernel(
    const h16* __restrict__ A, const h16* __restrict__ Bw,
    const float* __restrict__ bias,
    float* __restrict__ outf, float* __restrict__ hres,
    h16* __restrict__ o16, const float* __restrict__ posp,
    int M, int N, int K, int mode)
{
    const uint32_t sbase = smem_u32(dynsmem);
    const int tid = threadIdx.x;
    const int bm = blockIdx.y * 128;
    const int bn = blockIdx.x * 128;
    const int NC = K >> 6;
    const int w = tid >> 5, lane = tid & 31;
    const int wm = w & 3, wn = w >> 2;

    float acc[2][8][4];
#pragma unroll
    for (int mt = 0; mt < 2; mt++)
#pragma unroll
        for (int nt = 0; nt < 8; nt++)
#pragma unroll
            for (int r = 0; r < 4; r++) acc[mt][nt][r] = 0.f;

    auto load_stage = [&](int c, int slot) {
        const uint32_t sb = sbase + (uint32_t)slot * GSTAGE;
        const int k0 = c * 64;
#pragma unroll
        for (int t = 0; t < 2; t++) {
#pragma unroll
            for (int i = 0; i < 4; i++) {
                int s = tid + i * 256;
                int r = s >> 3, seg = s & 7;
                int grow = (t == 0) ? (bm + r) : (bn + r);
                int sz = 16;
                if (t == 0 && grow >= M) { grow = 0; sz = 0; }
                const h16* src = (t == 0 ? A : Bw) + (size_t)grow * K + k0 + seg * 8;
                uint32_t dst = sb + t * 16384 + SW128((uint32_t)(r * 128 + seg * 16));
                CP_ASYNC16(dst, src, sz);
            }
        }
        asm volatile("cp.async.commit_group;" ::: "memory");
    };

    load_stage(0, 0);
    if (NC > 1) load_stage(1, 1);

    int slot = 0;
    for (int c = 0; c < NC; c++) {
        if (c + 1 < NC) {
            asm volatile("cp.async.wait_group 1;" ::: "memory");
        } else {
            asm volatile("cp.async.wait_group 0;" ::: "memory");
        }
        __syncthreads();

        if (c + 2 < NC) {
            int ns = slot + 2;
            if (ns >= 3) ns -= 3;
            load_stage(c + 2, ns);
        }

        const uint32_t sb = sbase + (uint32_t)slot * GSTAGE;
        const uint32_t sa = sb, sbw = sb + 16384;

#pragma unroll
        for (int k16 = 0; k16 < 4; k16++) {
            const int kc = k16 * 16;
            uint32_t Af[2][4];
#pragma unroll
            for (int mt = 0; mt < 2; mt++) {
                uint32_t aoff = SW128((uint32_t)((wm * 32 + mt * 16 + (lane & 15)) * 128
                                                 + (kc + (lane >> 4) * 8) * 2));
                LDSM_X4(Af[mt][0], Af[mt][1], Af[mt][2], Af[mt][3], sa + aoff);
            }
            const int sub = lane >> 3, r8 = lane & 7;
            const int nloc = ((sub & 2) ? 8 : 0) + r8;
            const int kloc = kc + (sub & 1) * 8;
#pragma unroll
            for (int ng = 0; ng < 4; ng++) {
                uint32_t boff = SW128((uint32_t)((wn * 64 + ng * 16 + nloc) * 128 + kloc * 2));
                uint32_t Bf[4];
                LDSM_X4(Bf[0], Bf[1], Bf[2], Bf[3], sbw + boff);
#pragma unroll
                for (int mt = 0; mt < 2; mt++) {
#pragma unroll
                    for (int half = 0; half < 2; half++) {
                        const int nt = ng * 2 + half;
                        MMA16816(acc[mt][nt], Af[mt], Bf[half * 2], Bf[half * 2 + 1]);
                    }
                }
            }
        }

        slot++;
        if (slot >= 3) slot = 0;
    }

    // ---- epilogue ----
#pragma unroll
    for (int mt = 0; mt < 2; mt++) {
        const int r0 = bm + wm * 32 + mt * 16 + (lane >> 2);
#pragma unroll
        for (int nt = 0; nt < 8; nt++) {
            const int col = bn + wn * 64 + nt * 8 + (lane & 3) * 2;
            const float b0 = bias[col], b1 = bias[col + 1];
#pragma unroll
            for (int rr = 0; rr < 2; rr++) {
                const int row = r0 + rr * 8;
                if (row >= M) continue;
                float v0 = acc[mt][nt][rr * 2 + 0] + b0;
                float v1 = acc[mt][nt][rr * 2 + 1] + b1;
                size_t oi = (size_t)row * N + col;
                if (mode == 0) {
                    *(float2*)(outf + oi) = make_float2(v0, v1);
                } else if (mode == 1) {
                    float2* hp = (float2*)(hres + oi);
                    float2 t = *hp;
                    t.x += v0; t.y += v1;
                    *hp = t;
                } else if (mode == 2) {
                    float g0 = 0.5f * v0 * (1.0f + erff(v0 * 0.70710678118654752f));
                    float g1 = 0.5f * v1 * (1.0f + erff(v1 * 0.70710678118654752f));
                    __half2 hv = __floats2half2_rn(g0, g1);
                    *(uint32_t*)(o16 + oi) = *(uint32_t*)&hv;
                } else if (mode == 3) {
                    // patch-embed fused assemble (N == 768)
                    int bb = row / NPATCH;
                    int tt = row - bb * NPATCH;
                    size_t hrow = (size_t)(bb * NTOK + tt + 1);
                    const float* pp = posp + (size_t)(tt + 1) * D_ + col;
                    float2 o = make_float2(v0 + pp[0], v1 + pp[1]);
                    *(float2*)(hres + hrow * D_ + col) = o;
                } else if (mode == 5) {
                    // cls-row residual (N == 768, M == 32)
                    size_t hrow = (size_t)row * NTOK;
                    float2* hp = (float2*)(hres + hrow * D_ + col);
                    float2 t = *hp;
                    t.x += v0; t.y += v1;
                    *hp = t;
                } else {
                    // mode 6: interleaved hi/lo fp16 pair -> single STG.64
                    h16 h0 = __float2half_rn(v0), h1 = __float2half_rn(v1);
                    uint2 u;
                    u.x = pack_h2(h0, h1);
                    u.y = pack_h2(__float2half_rn(v0 - __half2float(h0)),
                                  __float2half_rn(v1 - __half2float(h1)));
                    ((uint2*)outf)[(size_t)row * (N >> 1) + (col >> 1)] = u;
                }
            }
        }
    }
}

// ---------------- cls row init: h[b*197] = cls + pos[0] ----------------
__global__ void cls_init_kernel(const float* __restrict__ cls, const float* __restrict__ pos,
                                float* __restrict__ h) {
    int i = blockIdx.x * blockDim.x + threadIdx.x;
    if (i < B_ * D_) {
        int b = i / D_, d = i - b * D_;
        h[(size_t)(b * NTOK) * D_ + d] = cls[d] + pos[d];
    }
}

// ---------------- batched weight transpose + fp16 (32n x 64k tile) ----------------
__global__ void wsplit_all_kernel(const float* __restrict__ W, h16* __restrict__ WT,
                                  int K, int N) {
    __shared__ float t[64][33];
    const size_t off = (size_t)blockIdx.z * K * N;
    const float* Wl = W + off;
    h16* WTl = WT + off;
    const int n0 = blockIdx.x * 32, k0 = blockIdx.y * 64;
    const int tx = threadIdx.x, ty = threadIdx.y;
#pragma unroll
    for (int j = 0; j < 8; j++) {
        int kk = ty + 8 * j;
        t[kk][tx] = Wl[(size_t)(k0 + kk) * N + n0 + tx];
    }
    __syncthreads();
#pragma unroll
    for (int j = 0; j < 4; j++) {
        int nl = ty + 8 * j;
        int kl = tx * 2;
        __half2 hv = __floats2half2_rn(t[kl][nl], t[kl + 1][nl]);
        *(uint32_t*)(WTl + (size_t)(n0 + nl) * K + k0 + kl) = *(uint32_t*)&hv;
    }
}

__global__ void split_kernel(const float* __restrict__ W, h16* __restrict__ o, int total) {
    for (int i = blockIdx.x * blockDim.x + threadIdx.x; i < total; i += gridDim.x * blockDim.x)
        o[i] = __float2half(W[i]);
}

// ---------------- patch extraction (fp16, float4 vectorized) ----------------
__global__ void extract_patches_kernel(const float* __restrict__ x, h16* __restrict__ p16) {
    const int total = PROWS * D_ / 4;
    for (int i = blockIdx.x * blockDim.x + threadIdx.x; i < total; i += gridDim.x * blockDim.x) {
        int idx = i * 4;
        int row = idx / D_;
        int k   = idx % D_;
        int b   = row / NPATCH;
        int t   = row % NPATCH;
        int ph  = t / 14, pw = t % 14;
        int cin = k >> 8;
        int rem = k & 255;
        int py  = rem >> 4, px = rem & 15;
        size_t src = (((size_t)b * 3 + cin) * 224 + (ph * 16 + py)) * 224 + (pw * 16 + px);
        float4 v = *(const float4*)(x + src);
        __half2 h0 = __floats2half2_rn(v.x, v.y);
        __half2 h1 = __floats2half2_rn(v.z, v.w);
        uint2 u;
        u.x = *(uint32_t*)&h0;
        u.y = *(uint32_t*)&h1;
        *(uint2*)(p16 + idx) = u;
    }
}

// ---------------- LayerNorm (fp32 out, final rows) ----------------
__global__ void ln_kernel(const float* __restrict__ x, const float* __restrict__ w,
                          const float* __restrict__ b, float* __restrict__ y,
                          int D, int inStride, int outStride) {
    const int row = blockIdx.x;
    const float* xr = x + (size_t)row * inStride;
    float* yr = y + (size_t)row * outStride;
    const int tid = threadIdx.x;
    float s = 0.f, q = 0.f;
    for (int i = tid; i < D; i += blockDim.x) { float v = xr[i]; s += v; q += v * v; }
    for (int o = 16; o; o >>= 1) { s += __shfl_xor_sync(~0u, s, o); q += __shfl_xor_sync(~0u, q, o); }
    __shared__ float ss[8], sq[8], mean_s, rstd_s;
    int wid = tid >> 5, lane = tid & 31;
    if (lane == 0) { ss[wid] = s; sq[wid] = q; }
    __syncthreads();
    if (tid == 0) {
        float ts = 0.f, tq = 0.f;
        for (int i = 0; i < (int)(blockDim.x >> 5); i++) { ts += ss[i]; tq += sq[i]; }
        float m = ts / D;
        mean_s = m;
        rstd_s = rsqrtf(tq / D - m * m + 1e-6f);
    }
    __syncthreads();
    float m = mean_s, rs = rstd_s;
    for (int i = tid; i < D; i += blockDim.x)
        yr[i] = (xr[i] - m) * rs * w[i] + b[i];
}

// ---------------- warp-per-row LayerNorm -> fp16 (D=768), strided ----------------
__global__ void __launch_bounds__(256) ln_h_warp_kernel(
    const float* __restrict__ x, const float* __restrict__ wv,
    const float* __restrict__ bv, h16* __restrict__ y16, int rows,
    size_t inStride, size_t outStride)
{
    const int row = blockIdx.x * 8 + (threadIdx.x >> 5);
    if (row >= rows) return;
    const int lane = threadIdx.x & 31;
    const float4* xr = (const float4*)(x + (size_t)row * inStride);
    float4 vals[6];
    float s = 0.f, q = 0.f;
#pragma unroll
    for (int k = 0; k < 6; k++) {
        float4 v = xr[lane + 32 * k];
        vals[k] = v;
        s += v.x + v.y + v.z + v.w;
        q += v.x * v.x + v.y * v.y + v.z * v.z + v.w * v.w;
    }
#pragma unroll
    for (int o = 16; o; o >>= 1) {
        s += __shfl_xor_sync(~0u, s, o);
        q += __shfl_xor_sync(~0u, q, o);
    }
    const float m = s / D_;
    const float rs = rsqrtf(q / D_ - m * m + 1e-6f);
    uint2* yo = (uint2*)(y16 + (size_t)row * outStride);
    const float4* w4 = (const float4*)wv;
    const float4* b4 = (const float4*)bv;
#pragma unroll
    for (int k = 0; k < 6; k++) {
        float4 v = vals[k];
        float4 ww = w4[lane + 32 * k];
        float4 bb = b4[lane + 32 * k];
        __half2 lo = __floats2half2_rn((v.x - m) * rs * ww.x + bb.x,
                                       (v.y - m) * rs * ww.y + bb.y);
        __half2 hi = __floats2half2_rn((v.z - m) * rs * ww.z + bb.z,
                                       (v.w - m) * rs * ww.w + bb.w);
        uint2 u;
        u.x = *(uint32_t*)&lo;
        u.y = *(uint32_t*)&hi;
        yo[lane + 32 * k] = u;
    }
}

// ---------------- attention: HMMA; QK 3-product, PV 2-product (V single fp16) ----------------
#define ASLAB 26624
#define AMMA_SMEM (5 * ASLAB)
__global__ void __launch_bounds__(256) attn_kernel(const uint2* __restrict__ qx,
                                                   h16* __restrict__ o16,
                                                   h16* __restrict__ oc, int ngroups) {
    char* sm = dynsmem;
    const uint32_t sbase = smem_u32(sm);
    const uint32_t Qh = sbase,      Ql = Qh + ASLAB;
    const uint32_t Kh = Ql + ASLAB, Kl = Kh + ASLAB;
    const uint32_t Vh = Kl + ASLAB;

    const int bh = blockIdx.x;
    const int b = bh / H_;
    const int h = bh % H_;
    const int tid = threadIdx.x;
    const int lane = tid & 31;
    const int w = tid >> 5;

    for (int idx = tid; idx < 208 * 32; idx += 256) {
        int m = idx >> 5, dp = idx & 31;
        uint2 uq = make_uint2(0, 0), uk = uq, uv = uq;
        if (m < NTOK) {
            const uint2* base = qx + (size_t)(b * NTOK + m) * (3 * D_ / 2) + h * 32 + dp;
            uq = base[0];
            uk = base[D_ / 2];
            uv = base[D_];
        }
        uint32_t off = SW128((uint32_t)(m * 128 + dp * 4));
        *(uint32_t*)(sm + (Qh - sbase) + off) = uq.x;
        *(uint32_t*)(sm + (Ql - sbase) + off) = uq.y;
        *(uint32_t*)(sm + (Kh - sbase) + off) = uk.x;
        *(uint32_t*)(sm + (Kl - sbase) + off) = uk.y;
        *(uint32_t*)(sm + (Vh - sbase) + off) = uv.x;
    }
    __syncthreads();

    const int c0 = (lane & 3) * 2;

    for (int mt = w; mt < ngroups; mt += 8) {
        float accS[26][4];
#pragma unroll
        for (int t = 0; t < 26; t++)
#pragma unroll
            for (int i = 0; i < 4; i++) accS[t][i] = 0.f;

#pragma unroll
        for (int kc = 0; kc < 4; kc++) {
            uint32_t Ah4[4], Al4[4];
            {
                uint32_t aoff = SW128((uint32_t)((mt * 16 + (lane & 15)) * 128
                                                 + (kc * 16 + (lane >> 4) * 8) * 2));
                LDSM_X4(Ah4[0], Ah4[1], Ah4[2], Ah4[3], Qh + aoff);
                LDSM_X4(Al4[0], Al4[1], Al4[2], Al4[3], Ql + aoff);
            }
            const int sub = lane >> 3, r8 = lane & 7;
            const int nloc = ((sub & 2) ? 8 : 0) + r8;
            const int kloc = kc * 16 + (sub & 1) * 8;
#pragma unroll
            for (int np = 0; np < 13; np++) {
                uint32_t boff = SW128((uint32_t)((np * 16 + nloc) * 128 + kloc * 2));
                uint32_t BH[4], BL[4];
                LDSM_X4(BH[0], BH[1], BH[2], BH[3], Kh + boff);
                LDSM_X4(BL[0], BL[1], BL[2], BL[3], Kl + boff);
                MMA16816(accS[2 * np], Ah4, BH[0], BH[1]);
                MMA16816(accS[2 * np], Ah4, BL[0], BL[1]);
                MMA16816(accS[2 * np], Al4, BH[0], BH[1]);
                MMA16816(accS[2 * np + 1], Ah4, BH[2], BH[3]);
                MMA16816(accS[2 * np + 1], Ah4, BL[2], BL[3]);
                MMA16816(accS[2 * np + 1], Al4, BH[2], BH[3]);
            }
        }

        float mx0 = -1e30f, mx1 = -1e30f;
#pragma unroll
        for (int t = 0; t < 26; t++) {
#pragma unroll
            for (int i = 0; i < 4; i++) {
                int col = t * 8 + c0 + (i & 1);
                float s = (col < NTOK) ? (accS[t][i] * 0.125f) : -1e30f;
                accS[t][i] = s;
                if (i < 2) mx0 = fmaxf(mx0, s);
                else       mx1 = fmaxf(mx1, s);
            }
        }
        mx0 = fmaxf(mx0, __shfl_xor_sync(~0u, mx0, 1));
        mx0 = fmaxf(mx0, __shfl_xor_sync(~0u, mx0, 2));
        mx1 = fmaxf(mx1, __shfl_xor_sync(~0u, mx1, 1));
        mx1 = fmaxf(mx1, __shfl_xor_sync(~0u, mx1, 2));
        float sum0 = 0.f, sum1 = 0.f;
#pragma unroll
        for (int t = 0; t < 26; t++) {
#pragma unroll
            for (int i = 0; i < 4; i++) {
                float e = expf(accS[t][i] - ((i < 2) ? mx0 : mx1));
                accS[t][i] = e;
                if (i < 2) sum0 += e;
                else       sum1 += e;
            }
        }
        sum0 += __shfl_xor_sync(~0u, sum0, 1);
        sum0 += __shfl_xor_sync(~0u, sum0, 2);
        sum1 += __shfl_xor_sync(~0u, sum1, 1);
        sum1 += __shfl_xor_sync(~0u, sum1, 2);
        const float inv0 = 1.f / sum0, inv1 = 1.f / sum1;

        float accO[8][4];
#pragma unroll
        for (int nt = 0; nt < 8; nt++)
#pragma unroll
            for (int i = 0; i < 4; i++) accO[nt][i] = 0.f;

        const int g = lane >> 3;
        const int vrow_loc = (g & 1) * 8 + (lane & 7);
        const int vcol_b = (g >> 1) * 16;

#pragma unroll
        for (int kk = 0; kk < 13; kk++) {
            float e0 = accS[2 * kk][0] * inv0, e1 = accS[2 * kk][1] * inv0;
            float e2 = accS[2 * kk][2] * inv1, e3 = accS[2 * kk][3] * inv1;
            float f0 = accS[2 * kk + 1][0] * inv0, f1 = accS[2 * kk + 1][1] * inv0;
            float f2 = accS[2 * kk + 1][2] * inv1, f3 = accS[2 * kk + 1][3] * inv1;
            h16 he0 = __float2half_rn(e0), he1 = __float2half_rn(e1);
            h16 he2 = __float2half_rn(e2), he3 = __float2half_rn(e3);
            h16 hf0 = __float2half_rn(f0), hf1 = __float2half_rn(f1);
            h16 hf2 = __float2half_rn(f2), hf3 = __float2half_rn(f3);
            uint32_t aH[4] = { pack_h2(he0, he1), pack_h2(he2, he3),
                               pack_h2(hf0, hf1), pack_h2(hf2, hf3) };
            uint32_t aL[4] = {
                pack_h2(__float2half_rn(e0 - __half2float(he0)), __float2half_rn(e1 - __half2float(he1))),
                pack_h2(__float2half_rn(e2 - __half2float(he2)), __float2half_rn(e3 - __half2float(he3))),
                pack_h2(__float2half_rn(f0 - __half2float(hf0)), __float2half_rn(f1 - __half2float(hf1))),
                pack_h2(__float2half_rn(f2 - __half2float(hf2)), __float2half_rn(f3 - __half2float(hf3))) };

            const int vrow = kk * 16 + vrow_loc;
#pragma unroll
            for (int vg = 0; vg < 4; vg++) {
                uint32_t voff = SW128((uint32_t)(vrow * 128 + vg * 32 + vcol_b));
                uint32_t VH[4];
                LDSM_X4_T(VH[0], VH[1], VH[2], VH[3], Vh + voff);
                MMA16816(accO[vg * 2], aH, VH[0], VH[1]);
                MMA16816(accO[vg * 2], aL, VH[0], VH[1]);
                MMA16816(accO[vg * 2 + 1], aH, VH[2], VH[3]);
                MMA16816(accO[vg * 2 + 1], aL, VH[2], VH[3]);
            }
        }

        const int r1 = mt * 16 + (lane >> 2);
        const int r2 = r1 + 8;
#pragma unroll
        for (int nt = 0; nt < 8; nt++) {
            const int col = h * DH + nt * 8 + c0;
            if (r1 < NTOK) {
                __half2 v = __floats2half2_rn(accO[nt][0], accO[nt][1]);
                *(uint32_t*)(o16 + (size_t)(b * NTOK + r1) * D_ + col) = *(uint32_t*)&v;
                if (ngroups == 1 && r1 == 0)
                    *(uint32_t*)(oc + (size_t)b * D_ + col) = *(uint32_t*)&v;
            }
            if (r2 < NTOK) {
                __half2 v = __floats2half2_rn(accO[nt][2], accO[nt][3]);
                *(uint32_t*)(o16 + (size_t)(b * NTOK + r2) * D_ + col) = *(uint32_t*)&v;
            }
        }
    }
}

// ---------------- host ----------------
extern "C" void kernel_launch(void* const* d_in, const int* in_sizes, int n_in,
                              void* d_out, int out_size) {
    const float* x       = (const float*)d_in[0];
    const float* conv_w  = (const float*)d_in[1];
    const float* conv_b  = (const float*)d_in[2];
    const float* cls_tok = (const float*)d_in[3];
    const float* pos     = (const float*)d_in[4];
    const float* ln1w    = (const float*)d_in[5];
    const float* ln1b    = (const float*)d_in[6];
    const float* qkvw    = (const float*)d_in[7];
    const float* qkvb    = (const float*)d_in[8];
    const float* projw   = (const float*)d_in[9];
    const float* projb   = (const float*)d_in[10];
    const float* ln2w    = (const float*)d_in[11];
    const float* ln2b    = (const float*)d_in[12];
    const float* fc1w    = (const float*)d_in[13];
    const float* fc1b    = (const float*)d_in[14];
    const float* fc2w    = (const float*)d_in[15];
    const float* fc2b    = (const float*)d_in[16];
    const float* lnfw    = (const float*)d_in[17];
    const float* lnfb    = (const float*)d_in[18];

    float *h;
    uint2 *qx;
    h16 *p16, *cw16, *y16, *o16, *mid16, *oc, *yc;
    h16 *wq, *wp, *w1, *w2;
    cudaGetSymbolAddress((void**)&h,     g_h);
    cudaGetSymbolAddress((void**)&qx,    g_qx);
    cudaGetSymbolAddress((void**)&p16,   g_p16);
    cudaGetSymbolAddress((void**)&cw16,  g_cw16);
    cudaGetSymbolAddress((void**)&y16,   g_y16);
    cudaGetSymbolAddress((void**)&o16,   g_o16);
    cudaGetSymbolAddress((void**)&mid16, g_mid16);
    cudaGetSymbolAddress((void**)&oc,    g_oc);
    cudaGetSymbolAddress((void**)&yc,    g_yc);
    cudaGetSymbolAddress((void**)&wq,    g_wqkv);
    cudaGetSymbolAddress((void**)&wp,    g_wproj);
    cudaGetSymbolAddress((void**)&w1,    g_wfc1);
    cudaGetSymbolAddress((void**)&w2,    g_wfc2);

    cudaFuncSetAttribute(attn_kernel, cudaFuncAttributeMaxDynamicSharedMemorySize, AMMA_SMEM);
    cudaFuncSetAttribute(gemm_mma_kernel, cudaFuncAttributeMaxDynamicSharedMemorySize, GSMEM_SZ);

    // ---- fork: weight conversion + cls_init on a side stream ----
    cudaStream_t s2;
    cudaEvent_t evFork, evJoin;
    cudaStreamCreateWithFlags(&s2, cudaStreamNonBlocking);
    cudaEventCreateWithFlags(&evFork, cudaEventDisableTiming);
    cudaEventCreateWithFlags(&evJoin, cudaEventDisableTiming);

    cudaEventRecord(evFork, 0);
    cudaStreamWaitEvent(s2, evFork, 0);
    {
        dim3 blk(32, 8);
        cls_init_kernel<<<(B_ * D_ + 255) / 256, 256, 0, s2>>>(cls_tok, pos, h);
        wsplit_all_kernel<<<dim3(3 * D_ / 32, D_ / 64, L_), blk, 0, s2>>>(qkvw, wq, D_, 3 * D_);
        wsplit_all_kernel<<<dim3(D_ / 32, D_ / 64, L_), blk, 0, s2>>>(projw, wp, D_, D_);
        wsplit_all_kernel<<<dim3(F_ / 32, D_ / 64, L_), blk, 0, s2>>>(fc1w, w1, D_, F_);
        wsplit_all_kernel<<<dim3(D_ / 32, F_ / 64, L_), blk, 0, s2>>>(fc2w, w2, F_, D_);
    }
    cudaEventRecord(evJoin, s2);

    // ---- patch embed on the main stream (independent of wq/wp/w1/w2) ----
    split_kernel<<<1024, 256>>>(conv_w, cw16, D_ * D_);
    extract_patches_kernel<<<1024, 256>>>(x, p16);
    gemm_mma_kernel<<<dim3(D_ / 128, PROWS / 128), 256, GSMEM_SZ>>>(
        p16, cw16, conv_b, nullptr, h, nullptr, pos, PROWS, D_, D_, 3);

    // join: everything after needs the converted weights (+ cls rows of h)
    cudaStreamWaitEvent(0, evJoin, 0);

    const int mb = (ROWS + 127) / 128;   // 50
    const int lnb = (ROWS + 7) / 8;      // 788
    for (int l = 0; l < L_; l++) {
        const bool last = (l == L_ - 1);

        ln_h_warp_kernel<<<lnb, 256>>>(h, ln1w + l * D_, ln1b + l * D_, y16, ROWS,
                                       (size_t)D_, (size_t)D_);
        gemm_mma_kernel<<<dim3(3 * D_ / 128, mb), 256, GSMEM_SZ>>>(
            y16, wq + (size_t)l * 3 * D_ * D_, qkvb + (size_t)l * 3 * D_,
            (float*)qx, nullptr, nullptr, nullptr, ROWS, 3 * D_, D_, 6);
        attn_kernel<<<B_ * H_, 256, AMMA_SMEM>>>(qx, o16, oc, last ? 1 : 13);

        if (!last) {
            gemm_mma_kernel<<<dim3(D_ / 128, mb), 256, GSMEM_SZ>>>(
                o16, wp + (size_t)l * D_ * D_, projb + (size_t)l * D_,
                nullptr, h, nullptr, nullptr, ROWS, D_, D_, 1);
            ln_h_warp_kernel<<<lnb, 256>>>(h, ln2w + l * D_, ln2b + l * D_, y16, ROWS,
                                           (size_t)D_, (size_t)D_);
            gemm_mma_kernel<<<dim3(F_ / 128, mb), 256, GSMEM_SZ>>>(
                y16, w1 + (size_t)l * F_ * D_, fc1b + (size_t)l * F_,
                nullptr, nullptr, mid16, nullptr, ROWS, F_, D_, 2);
            gemm_mma_kernel<<<dim3(D_ / 128, mb), 256, GSMEM_SZ>>>(
                mid16, w2 + (size_t)l * D_ * F_, fc2b + (size_t)l * D_,
                nullptr, h, nullptr, nullptr, ROWS, D_, F_, 1);
        } else {
            // last layer: only cls-token rows feed the output (oc filled by attention)
            gemm_mma_kernel<<<dim3(D_ / 128, 1), 256, GSMEM_SZ>>>(
                oc, wp + (size_t)l * D_ * D_, projb + (size_t)l * D_,
                nullptr, h, nullptr, nullptr, B_, D_, D_, 5);
            ln_h_warp_kernel<<<(B_ + 7) / 8, 256>>>(h, ln2w + l * D_, ln2b + l * D_, yc, B_,
                                                    (size_t)NTOK * D_, (size_t)D_);
            gemm_mma_kernel<<<dim3(F_ / 128, 1), 256, GSMEM_SZ>>>(
                yc, w1 + (size_t)l * F_ * D_, fc1b + (size_t)l * F_,
                nullptr, nullptr, mid16, nullptr, B_, F_, D_, 2);
            gemm_mma_kernel<<<dim3(D_ / 128, 1), 256, GSMEM_SZ>>>(
                mid16, w2 + (size_t)l * D_ * F_, fc2b + (size_t)l * D_,
                nullptr, h, nullptr, nullptr, B_, D_, F_, 5);
        }
    }

    ln_kernel<<<B_, 256>>>(h, lnfw, lnfb, (float*)d_out, D_, NTOK * D_, D_);
}